// round 1
// baseline (speedup 1.0000x reference)
#include <cuda_runtime.h>
#include <stdint.h>

#define S    4096
#define MDIM 1024
#define E    8
#define CAP  1024   // TOP_K * ceil(S/E) = 2*512

// ---------------- scratch (device globals; no allocation) ----------------
__device__ int   g_e0[S];
__device__ float g_gate[S];
__device__ float g_probs[S * E];
__device__ int   g_tok[E * CAP];
__device__ int   g_ne[E];

// ---------------- kernel 1: gating ----------------
// 1 warp per token. wg (8x1024 = 32KB) staged in shared.
__global__ void __launch_bounds__(256) gate_kernel(const float* __restrict__ x,
                                                   const float* __restrict__ wg) {
    __shared__ float wgs[E * MDIM];
    int tid = threadIdx.x;
    for (int i = tid; i < E * MDIM / 4; i += 256)
        ((float4*)wgs)[i] = ((const float4*)wg)[i];
    __syncthreads();

    int warp = tid >> 5, lane = tid & 31;
    int s = blockIdx.x * 8 + warp;

    const float4* xr = (const float4*)(x + (size_t)s * MDIM);
    float acc[E];
#pragma unroll
    for (int e = 0; e < E; e++) acc[e] = 0.f;

#pragma unroll
    for (int it = 0; it < MDIM / 128; it++) {
        int k4 = it * 32 + lane;
        float4 xv = xr[k4];
#pragma unroll
        for (int e = 0; e < E; e++) {
            float4 wv = ((const float4*)(wgs + e * MDIM))[k4];
            acc[e] += xv.x * wv.x + xv.y * wv.y + xv.z * wv.z + xv.w * wv.w;
        }
    }
#pragma unroll
    for (int e = 0; e < E; e++) {
#pragma unroll
        for (int off = 16; off; off >>= 1)
            acc[e] += __shfl_xor_sync(0xffffffffu, acc[e], off);
    }
    if (lane == 0) {
        // argmax (first index on ties, matching jax top_k)
        float mx = acc[0]; int ei = 0;
#pragma unroll
        for (int e = 1; e < E; e++) if (acc[e] > mx) { mx = acc[e]; ei = e; }
        float ex[E]; float sum = 0.f;
#pragma unroll
        for (int e = 0; e < E; e++) { ex[e] = expf(acc[e] - mx); sum += ex[e]; }
        float inv = 1.f / sum;
#pragma unroll
        for (int e = 0; e < E; e++) g_probs[s * E + e] = ex[e] * inv;
        g_e0[s]   = ei;
        g_gate[s] = ex[ei] * inv;
    }
}

// ---------------- kernel 2: ordered prefix scan, token lists, loss ----------------
// Single block, deterministic. 256 threads x 16 consecutive tokens each.
__global__ void __launch_bounds__(256) scan_kernel(float* __restrict__ d_out,
                                                   long long out_size) {
    const int T = 256, CH = S / T; // 16
    __shared__ int   cnt[T][E];
    __shared__ float mesh[T][E];
    __shared__ int   tot[E];

    int tid = threadIdx.x;
    int   c[E]; float m[E];
#pragma unroll
    for (int e = 0; e < E; e++) { c[e] = 0; m[e] = 0.f; }

    int base_s = tid * CH;
    for (int i = 0; i < CH; i++) {
        int s = base_s + i;
        c[g_e0[s]]++;
#pragma unroll
        for (int e = 0; e < E; e++) m[e] += g_probs[s * E + e];
    }
#pragma unroll
    for (int e = 0; e < E; e++) { cnt[tid][e] = c[e]; mesh[tid][e] = m[e]; }
    __syncthreads();

    // serial exclusive scan per expert (8 threads, 256 steps — cheap, deterministic)
    if (tid < E) {
        int run = 0;
        for (int t = 0; t < T; t++) { int v = cnt[t][tid]; cnt[t][tid] = run; run += v; }
        tot[tid] = run;
        g_ne[tid] = run < CAP ? run : CAP;
    }
    __syncthreads();

    int off[E];
#pragma unroll
    for (int e = 0; e < E; e++) off[e] = cnt[tid][e];
    for (int i = 0; i < CH; i++) {
        int s = base_s + i;
        int e = g_e0[s];
        int loc = off[e]++;
        if (loc < CAP) g_tok[e * CAP + loc] = s;
        // dropped tokens: result row stays 0 (memset)
    }

    // deterministic tree reduce for me
    __syncthreads();
    for (int stride = T / 2; stride; stride >>= 1) {
        if (tid < stride) {
#pragma unroll
            for (int e = 0; e < E; e++) mesh[tid][e] += mesh[tid + stride][e];
        }
        __syncthreads();
    }
    if (tid == 0 && out_size > (long long)S * MDIM) {
        float loss = 0.f;
#pragma unroll
        for (int e = 0; e < E; e++) loss += mesh[0][e] * (float)tot[e];
        loss *= (float)E / ((float)S * (float)S);
        d_out[(long long)S * MDIM] = loss;
    }
}

// ---------------- kernel 3: grouped GEMM ----------------
// result[tok,:] = gate[tok] * x[tok,:] @ we[e]   for tok in expert e's kept list.
// BM=64, BN=64, BK=16, 256 threads, 4x4 micro-tile per thread.
#define BM 64
#define BN 64
#define BK 16

__global__ void __launch_bounds__(256) moe_gemm(const float* __restrict__ x,
                                                const float* __restrict__ we,
                                                float* __restrict__ out) {
    int e  = blockIdx.z;
    int ne = g_ne[e];
    int r0 = blockIdx.y * BM;
    if (r0 >= ne) return;
    int n0 = blockIdx.x * BN;

    __shared__ float As[BK][BM];
    __shared__ float Bs[BK][BN];
    __shared__ int   toks[BM];
    __shared__ float gts[BM];

    int tid = threadIdx.x;
    if (tid < BM) {
        int r = r0 + tid;
        int t = (r < ne) ? g_tok[e * CAP + r] : -1;
        toks[tid] = t;
        gts[tid]  = (t >= 0) ? g_gate[t] : 0.f;
    }
    __syncthreads();

    const float* wbase = we + (size_t)e * MDIM * MDIM;

    int tx = tid & 15;   // n
    int ty = tid >> 4;   // m
    float acc[4][4];
#pragma unroll
    for (int i = 0; i < 4; i++)
#pragma unroll
        for (int j = 0; j < 4; j++) acc[i][j] = 0.f;

    // A-load mapping: row = tid/4 (0..63), kq = tid%4 (float4 within BK)
    int arow = tid >> 2, akq = tid & 3;
    int at = toks[arow];
    // B-load mapping: kr = tid/16 (0..15), nq = tid%16 (float4 within BN)
    int bkr = tid >> 4, bnq = tid & 15;

    for (int k0 = 0; k0 < MDIM; k0 += BK) {
        float4 av = make_float4(0.f, 0.f, 0.f, 0.f);
        if (at >= 0)
            av = *(const float4*)(x + (size_t)at * MDIM + k0 + akq * 4);
        float4 bv = *(const float4*)(wbase + (size_t)(k0 + bkr) * MDIM + n0 + bnq * 4);
        __syncthreads();  // protect previous tile's reads
        As[akq * 4 + 0][arow] = av.x;
        As[akq * 4 + 1][arow] = av.y;
        As[akq * 4 + 2][arow] = av.z;
        As[akq * 4 + 3][arow] = av.w;
        *(float4*)&Bs[bkr][bnq * 4] = bv;
        __syncthreads();

#pragma unroll
        for (int k = 0; k < BK; k++) {
            float4 a = *(const float4*)&As[k][ty * 4];
            float4 b = *(const float4*)&Bs[k][tx * 4];
            float av4[4] = {a.x, a.y, a.z, a.w};
            float bv4[4] = {b.x, b.y, b.z, b.w};
#pragma unroll
            for (int i = 0; i < 4; i++)
#pragma unroll
                for (int j = 0; j < 4; j++)
                    acc[i][j] += av4[i] * bv4[j];
        }
    }

#pragma unroll
    for (int i = 0; i < 4; i++) {
        int r = r0 + ty * 4 + i;
        if (r < ne) {
            int   t = toks[ty * 4 + i];
            float g = gts[ty * 4 + i];
            float4 o;
            o.x = g * acc[i][0];
            o.y = g * acc[i][1];
            o.z = g * acc[i][2];
            o.w = g * acc[i][3];
            *(float4*)(out + (size_t)t * MDIM + n0 + tx * 4) = o;
        }
    }
}

// ---------------- launcher ----------------
extern "C" void kernel_launch(void* const* d_in, const int* in_sizes, int n_in,
                              void* d_out, int out_size) {
    const float* x  = (const float*)d_in[0];  // (4096, 1024)
    const float* wg = (const float*)d_in[1];  // (8, 1024)
    const float* we = (const float*)d_in[2];  // (8, 1024, 1024)
    float* out = (float*)d_out;

    // zero the result region (dropped tokens must be 0)
    cudaMemsetAsync(d_out, 0, sizeof(float) * (size_t)S * MDIM, 0);

    gate_kernel<<<S / 8, 256>>>(x, wg);
    scan_kernel<<<1, 256>>>(out, (long long)out_size);

    dim3 grid(MDIM / BN, CAP / BM, E);
    moe_gemm<<<grid, 256>>>(x, we, out);
}

// round 2
// speedup vs baseline: 1.2446x; 1.2446x over previous
#include <cuda_runtime.h>
#include <stdint.h>

#define S    4096
#define MDIM 1024
#define E    8
#define CAP  1024   // TOP_K * ceil(S/E) = 2*512

// ---------------- scratch (device globals; no allocation) ----------------
__device__ int   g_e0[S];
__device__ float g_gate[S];
__device__ float g_probs[S * E];
__device__ int   g_tok[E * CAP];
__device__ int   g_ne[E];

// ---------------- kernel 1: gating ----------------
// 1 warp per token. wg (8x1024 = 32KB) staged in shared.
__global__ void __launch_bounds__(256) gate_kernel(const float* __restrict__ x,
                                                   const float* __restrict__ wg) {
    __shared__ float wgs[E * MDIM];
    int tid = threadIdx.x;
    for (int i = tid; i < E * MDIM / 4; i += 256)
        ((float4*)wgs)[i] = ((const float4*)wg)[i];
    __syncthreads();

    int warp = tid >> 5, lane = tid & 31;
    int s = blockIdx.x * 8 + warp;

    const float4* xr = (const float4*)(x + (size_t)s * MDIM);
    float acc[E];
#pragma unroll
    for (int e = 0; e < E; e++) acc[e] = 0.f;

#pragma unroll
    for (int it = 0; it < MDIM / 128; it++) {
        int k4 = it * 32 + lane;
        float4 xv = xr[k4];
#pragma unroll
        for (int e = 0; e < E; e++) {
            float4 wv = ((const float4*)(wgs + e * MDIM))[k4];
            acc[e] += xv.x * wv.x + xv.y * wv.y + xv.z * wv.z + xv.w * wv.w;
        }
    }
#pragma unroll
    for (int e = 0; e < E; e++) {
#pragma unroll
        for (int off = 16; off; off >>= 1)
            acc[e] += __shfl_xor_sync(0xffffffffu, acc[e], off);
    }
    if (lane == 0) {
        // argmax (first index on ties, matching jax top_k)
        float mx = acc[0]; int ei = 0;
#pragma unroll
        for (int e = 1; e < E; e++) if (acc[e] > mx) { mx = acc[e]; ei = e; }
        float ex[E]; float sum = 0.f;
#pragma unroll
        for (int e = 0; e < E; e++) { ex[e] = expf(acc[e] - mx); sum += ex[e]; }
        float inv = 1.f / sum;
#pragma unroll
        for (int e = 0; e < E; e++) g_probs[s * E + e] = ex[e] * inv;
        g_e0[s]   = ei;
        g_gate[s] = ex[ei] * inv;
    }
}

// ---------------- kernel 2: ordered prefix scan, token lists, loss ----------------
__global__ void __launch_bounds__(256) scan_kernel(float* __restrict__ d_out,
                                                   long long out_size) {
    const int T = 256, CH = S / T; // 16
    __shared__ int   cnt[T][E];
    __shared__ float mesh[T][E];
    __shared__ int   tot[E];

    int tid = threadIdx.x;
    int   c[E]; float m[E];
#pragma unroll
    for (int e = 0; e < E; e++) { c[e] = 0; m[e] = 0.f; }

    int base_s = tid * CH;
    for (int i = 0; i < CH; i++) {
        int s = base_s + i;
        c[g_e0[s]]++;
#pragma unroll
        for (int e = 0; e < E; e++) m[e] += g_probs[s * E + e];
    }
#pragma unroll
    for (int e = 0; e < E; e++) { cnt[tid][e] = c[e]; mesh[tid][e] = m[e]; }
    __syncthreads();

    if (tid < E) {
        int run = 0;
        for (int t = 0; t < T; t++) { int v = cnt[t][tid]; cnt[t][tid] = run; run += v; }
        tot[tid] = run;
        g_ne[tid] = run < CAP ? run : CAP;
    }
    __syncthreads();

    int off[E];
#pragma unroll
    for (int e = 0; e < E; e++) off[e] = cnt[tid][e];
    for (int i = 0; i < CH; i++) {
        int s = base_s + i;
        int e = g_e0[s];
        int loc = off[e]++;
        if (loc < CAP) g_tok[e * CAP + loc] = s;
    }

    __syncthreads();
    for (int stride = T / 2; stride; stride >>= 1) {
        if (tid < stride) {
#pragma unroll
            for (int e = 0; e < E; e++) mesh[tid][e] += mesh[tid + stride][e];
        }
        __syncthreads();
    }
    if (tid == 0 && out_size > (long long)S * MDIM) {
        float loss = 0.f;
#pragma unroll
        for (int e = 0; e < E; e++) loss += mesh[0][e] * (float)tot[e];
        loss *= (float)E / ((float)S * (float)S);
        d_out[(long long)S * MDIM] = loss;
    }
}

// ---------------- kernel 3: grouped GEMM, 128x128x8, double-buffered ----------------
#define BM 128
#define BN 128
#define BK 8

__global__ void __launch_bounds__(256, 2) moe_gemm(const float* __restrict__ x,
                                                   const float* __restrict__ we,
                                                   float* __restrict__ out) {
    int e  = blockIdx.z;
    int ne = g_ne[e];
    int r0 = blockIdx.y * BM;
    if (r0 >= ne) return;
    int n0 = blockIdx.x * BN;

    __shared__ float As[2][BK][BM];
    __shared__ float Bs[2][BK][BN];
    __shared__ int   toks[BM];
    __shared__ float gts[BM];

    int tid = threadIdx.x;
    if (tid < BM) {
        int r = r0 + tid;
        int t = (r < ne) ? g_tok[e * CAP + r] : -1;
        toks[tid] = t;
        gts[tid]  = (t >= 0) ? g_gate[t] : 0.f;
    }
    __syncthreads();

    const float* wbase = we + (size_t)e * MDIM * MDIM;

    // A-load mapping: 128x8 tile = 256 float4; arow = tid/2, akq = tid%2
    int arow = tid >> 1, akq = tid & 1;
    int at = toks[arow];
    const float* aptr = (at >= 0) ? (x + (size_t)at * MDIM + akq * 4) : x;
    // B-load mapping: 8x128 tile = 256 float4; bkr = tid/32, bnq = tid%32
    int bkr = tid >> 5, bnq = tid & 31;
    const float* bptr = wbase + (size_t)bkr * MDIM + n0 + bnq * 4;

    // prologue: load tile 0 into buffer 0
    float4 av = make_float4(0.f, 0.f, 0.f, 0.f);
    if (at >= 0) av = *(const float4*)(aptr);
    float4 bv = *(const float4*)(bptr);
    As[0][akq * 4 + 0][arow] = av.x;
    As[0][akq * 4 + 1][arow] = av.y;
    As[0][akq * 4 + 2][arow] = av.z;
    As[0][akq * 4 + 3][arow] = av.w;
    *(float4*)&Bs[0][bkr][bnq * 4] = bv;
    __syncthreads();

    int ty = tid >> 4, tx = tid & 15;  // 16x16 thread grid, 8x8 micro-tile
    float acc[8][8];
#pragma unroll
    for (int i = 0; i < 8; i++)
#pragma unroll
        for (int j = 0; j < 8; j++) acc[i][j] = 0.f;

    for (int k0 = BK; k0 <= MDIM; k0 += BK) {
        int cur = ((k0 / BK) - 1) & 1;
        int nxt = cur ^ 1;

        // prefetch next tile into registers (overlaps with compute below)
        float4 pav = make_float4(0.f, 0.f, 0.f, 0.f);
        float4 pbv;
        bool more = (k0 < MDIM);
        if (more) {
            if (at >= 0) pav = *(const float4*)(aptr + k0);
            pbv = *(const float4*)(bptr + (size_t)k0 * MDIM);
        }

#pragma unroll
        for (int k = 0; k < BK; k++) {
            float4 a0 = *(const float4*)&As[cur][k][ty * 8];
            float4 a1 = *(const float4*)&As[cur][k][ty * 8 + 4];
            float4 b0 = *(const float4*)&Bs[cur][k][tx * 8];
            float4 b1 = *(const float4*)&Bs[cur][k][tx * 8 + 4];
            float ar[8] = {a0.x, a0.y, a0.z, a0.w, a1.x, a1.y, a1.z, a1.w};
            float br[8] = {b0.x, b0.y, b0.z, b0.w, b1.x, b1.y, b1.z, b1.w};
#pragma unroll
            for (int i = 0; i < 8; i++)
#pragma unroll
                for (int j = 0; j < 8; j++)
                    acc[i][j] += ar[i] * br[j];
        }

        if (more) {
            As[nxt][akq * 4 + 0][arow] = pav.x;
            As[nxt][akq * 4 + 1][arow] = pav.y;
            As[nxt][akq * 4 + 2][arow] = pav.z;
            As[nxt][akq * 4 + 3][arow] = pav.w;
            *(float4*)&Bs[nxt][bkr][bnq * 4] = pbv;
        }
        __syncthreads();
    }

    // epilogue: scale by gate, scatter rows
#pragma unroll
    for (int i = 0; i < 8; i++) {
        int lr = ty * 8 + i;
        int r = r0 + lr;
        if (r < ne) {
            int   t = toks[lr];
            float g = gts[lr];
            float* orow = out + (size_t)t * MDIM + n0 + tx * 8;
            float4 o0, o1;
            o0.x = g * acc[i][0]; o0.y = g * acc[i][1];
            o0.z = g * acc[i][2]; o0.w = g * acc[i][3];
            o1.x = g * acc[i][4]; o1.y = g * acc[i][5];
            o1.z = g * acc[i][6]; o1.w = g * acc[i][7];
            *(float4*)(orow)     = o0;
            *(float4*)(orow + 4) = o1;
        }
    }
}

// ---------------- launcher ----------------
extern "C" void kernel_launch(void* const* d_in, const int* in_sizes, int n_in,
                              void* d_out, int out_size) {
    const float* x  = (const float*)d_in[0];  // (4096, 1024)
    const float* wg = (const float*)d_in[1];  // (8, 1024)
    const float* we = (const float*)d_in[2];  // (8, 1024, 1024)
    float* out = (float*)d_out;

    cudaMemsetAsync(d_out, 0, sizeof(float) * (size_t)S * MDIM, 0);

    gate_kernel<<<S / 8, 256>>>(x, wg);
    scan_kernel<<<1, 256>>>(out, (long long)out_size);

    dim3 grid(MDIM / BN, CAP / BM, E);
    moe_gemm<<<grid, 256>>>(x, we, out);
}

// round 4
// speedup vs baseline: 2.1453x; 1.7237x over previous
#include <cuda_runtime.h>
#include <cuda_bf16.h>
#include <stdint.h>

#define S    4096
#define MDIM 1024
#define E    8
#define CAP  1024
#define BM   128
#define BN   128
#define BK   32
#define NKC  (MDIM / BK)   // 32

// ---------------- scratch (device globals; no allocation) ----------------
__device__ int   g_e0[S];
__device__ float g_gate[S];
__device__ float g_probs[S * E];
__device__ int   g_tok[E * CAP];
__device__ int   g_ne[E];
__device__ __nv_bfloat16 g_xh[S * MDIM];
__device__ __nv_bfloat16 g_xl[S * MDIM];
__device__ __nv_bfloat16 g_weh[E * MDIM * MDIM];  // [e][k][n], n contiguous
__device__ __nv_bfloat16 g_wel[E * MDIM * MDIM];

__device__ __forceinline__ uint32_t smem_u32(const void* p) {
    uint32_t a;
    asm("{ .reg .u64 t; cvta.to.shared.u64 t, %1; cvt.u32.u64 %0, t; }" : "=r"(a) : "l"(p));
    return a;
}
__device__ __forceinline__ void cp_async16(uint32_t dst, const void* src, uint32_t bytes) {
    asm volatile("cp.async.cg.shared.global [%0], [%1], 16, %2;"
                 :: "r"(dst), "l"(src), "r"(bytes) : "memory");
}
#define CP_COMMIT() asm volatile("cp.async.commit_group;" ::: "memory")
#define CP_WAIT(n)  asm volatile("cp.async.wait_group %0;" :: "n"(n) : "memory")

__device__ __forceinline__ void ldmat_x4(uint32_t* r, uint32_t addr) {
    asm volatile("ldmatrix.sync.aligned.m8n8.x4.shared.b16 {%0,%1,%2,%3}, [%4];"
                 : "=r"(r[0]), "=r"(r[1]), "=r"(r[2]), "=r"(r[3]) : "r"(addr));
}
__device__ __forceinline__ void ldmat_x4_t(uint32_t* r, uint32_t addr) {
    asm volatile("ldmatrix.sync.aligned.m8n8.x4.trans.shared.b16 {%0,%1,%2,%3}, [%4];"
                 : "=r"(r[0]), "=r"(r[1]), "=r"(r[2]), "=r"(r[3]) : "r"(addr));
}
__device__ __forceinline__ void mma16816(float* c, const uint32_t* a, uint32_t b0, uint32_t b1) {
    asm volatile("mma.sync.aligned.m16n8k16.row.col.f32.bf16.bf16.f32 "
                 "{%0,%1,%2,%3}, {%4,%5,%6,%7}, {%8,%9}, {%0,%1,%2,%3};"
                 : "+f"(c[0]), "+f"(c[1]), "+f"(c[2]), "+f"(c[3])
                 : "r"(a[0]), "r"(a[1]), "r"(a[2]), "r"(a[3]), "r"(b0), "r"(b1));
}

// ---------------- kernel 1: gating ----------------
__global__ void __launch_bounds__(256) gate_kernel(const float* __restrict__ x,
                                                   const float* __restrict__ wg) {
    __shared__ float wgs[E * MDIM];
    int tid = threadIdx.x;
    for (int i = tid; i < E * MDIM / 4; i += 256)
        ((float4*)wgs)[i] = ((const float4*)wg)[i];
    __syncthreads();

    int warp = tid >> 5, lane = tid & 31;
    int s = blockIdx.x * 8 + warp;
    const float4* xr = (const float4*)(x + (size_t)s * MDIM);
    float acc[E];
#pragma unroll
    for (int e = 0; e < E; e++) acc[e] = 0.f;
#pragma unroll
    for (int it = 0; it < MDIM / 128; it++) {
        int k4 = it * 32 + lane;
        float4 xv = xr[k4];
#pragma unroll
        for (int e = 0; e < E; e++) {
            float4 wv = ((const float4*)(wgs + e * MDIM))[k4];
            acc[e] += xv.x * wv.x + xv.y * wv.y + xv.z * wv.z + xv.w * wv.w;
        }
    }
#pragma unroll
    for (int e = 0; e < E; e++) {
#pragma unroll
        for (int off = 16; off; off >>= 1)
            acc[e] += __shfl_xor_sync(0xffffffffu, acc[e], off);
    }
    if (lane == 0) {
        float mx = acc[0]; int ei = 0;
#pragma unroll
        for (int e = 1; e < E; e++) if (acc[e] > mx) { mx = acc[e]; ei = e; }
        float ex[E]; float sum = 0.f;
#pragma unroll
        for (int e = 0; e < E; e++) { ex[e] = expf(acc[e] - mx); sum += ex[e]; }
        float inv = 1.f / sum;
#pragma unroll
        for (int e = 0; e < E; e++) g_probs[s * E + e] = ex[e] * inv;
        g_e0[s]   = ei;
        g_gate[s] = ex[ei] * inv;
    }
}

// ---------------- kernel 2: ordered prefix scan + loss ----------------
__global__ void __launch_bounds__(256) scan_kernel(float* __restrict__ d_out,
                                                   long long out_size) {
    const int T = 256, CH = S / T;
    __shared__ int   cnt[T][E];
    __shared__ float mesh[T][E];
    __shared__ int   tot[E];
    int tid = threadIdx.x;
    int   c[E]; float m[E];
#pragma unroll
    for (int e = 0; e < E; e++) { c[e] = 0; m[e] = 0.f; }
    int base_s = tid * CH;
    for (int i = 0; i < CH; i++) {
        int s = base_s + i;
        c[g_e0[s]]++;
#pragma unroll
        for (int e = 0; e < E; e++) m[e] += g_probs[s * E + e];
    }
#pragma unroll
    for (int e = 0; e < E; e++) { cnt[tid][e] = c[e]; mesh[tid][e] = m[e]; }
    __syncthreads();
    if (tid < E) {
        int run = 0;
        for (int t = 0; t < T; t++) { int v = cnt[t][tid]; cnt[t][tid] = run; run += v; }
        tot[tid] = run;
        g_ne[tid] = run < CAP ? run : CAP;
    }
    __syncthreads();
    int off[E];
#pragma unroll
    for (int e = 0; e < E; e++) off[e] = cnt[tid][e];
    for (int i = 0; i < CH; i++) {
        int s = base_s + i;
        int e = g_e0[s];
        int loc = off[e]++;
        if (loc < CAP) g_tok[e * CAP + loc] = s;
    }
    __syncthreads();
    for (int stride = T / 2; stride; stride >>= 1) {
        if (tid < stride) {
#pragma unroll
            for (int e = 0; e < E; e++) mesh[tid][e] += mesh[tid + stride][e];
        }
        __syncthreads();
    }
    if (tid == 0 && out_size > (long long)S * MDIM) {
        float loss = 0.f;
#pragma unroll
        for (int e = 0; e < E; e++) loss += mesh[0][e] * (float)tot[e];
        loss *= (float)E / ((float)S * (float)S);
        d_out[(long long)S * MDIM] = loss;
    }
}

// ---------------- prep: fp32 -> bf16 hi/lo splits ----------------
__global__ void __launch_bounds__(256) split_x_kernel(const float* __restrict__ x) {
    int i = blockIdx.x * 256 + threadIdx.x;
    float4 v = ((const float4*)x)[i];
    __nv_bfloat16 h0 = __float2bfloat16(v.x), h1 = __float2bfloat16(v.y);
    __nv_bfloat16 h2 = __float2bfloat16(v.z), h3 = __float2bfloat16(v.w);
    __nv_bfloat162* oh = (__nv_bfloat162*)g_xh + (size_t)i * 2;
    __nv_bfloat162* ol = (__nv_bfloat162*)g_xl + (size_t)i * 2;
    oh[0] = __halves2bfloat162(h0, h1);
    oh[1] = __halves2bfloat162(h2, h3);
    ol[0] = __halves2bfloat162(__float2bfloat16(v.x - __bfloat162float(h0)),
                               __float2bfloat16(v.y - __bfloat162float(h1)));
    ol[1] = __halves2bfloat162(__float2bfloat16(v.z - __bfloat162float(h2)),
                               __float2bfloat16(v.w - __bfloat162float(h3)));
}
__global__ void __launch_bounds__(256) split_we_kernel(const float* __restrict__ we) {
    size_t i = (size_t)blockIdx.x * 256 + threadIdx.x;
    float4 v = ((const float4*)we)[i];
    __nv_bfloat16 h0 = __float2bfloat16(v.x), h1 = __float2bfloat16(v.y);
    __nv_bfloat16 h2 = __float2bfloat16(v.z), h3 = __float2bfloat16(v.w);
    __nv_bfloat162* oh = (__nv_bfloat162*)g_weh + i * 2;
    __nv_bfloat162* ol = (__nv_bfloat162*)g_wel + i * 2;
    oh[0] = __halves2bfloat162(h0, h1);
    oh[1] = __halves2bfloat162(h2, h3);
    ol[0] = __halves2bfloat162(__float2bfloat16(v.x - __bfloat162float(h0)),
                               __float2bfloat16(v.y - __bfloat162float(h1)));
    ol[1] = __halves2bfloat162(__float2bfloat16(v.z - __bfloat162float(h2)),
                               __float2bfloat16(v.w - __bfloat162float(h3)));
}

// ---------------- kernel 3: grouped GEMM via mma.sync bf16 x3 ----------------
// SMEM layout (dynamic): A rows padded to 80B, B rows padded to 272B.
#define A_ROWB 80
#define B_ROWB 272
#define A_TILE (BM * A_ROWB)          // 10240
#define B_TILE (BK * B_ROWB)          // 8704
#define OFF_AH 0
#define OFF_AL (2 * A_TILE)           // 20480
#define OFF_BH (4 * A_TILE)           // 40960
#define OFF_BL (4 * A_TILE + 2 * B_TILE)  // 58368
#define SMEM_BYTES (4 * A_TILE + 4 * B_TILE)  // 75776

__global__ void __launch_bounds__(256) moe_gemm_mma(float* __restrict__ out) {
    int e  = blockIdx.z;
    int ne = g_ne[e];
    int r0 = blockIdx.y * BM;
    if (r0 >= ne) return;
    int n0 = blockIdx.x * BN;

    extern __shared__ __align__(16) char sm[];
    uint32_t sb = smem_u32(sm);
    __shared__ int   s_toks[BM];
    __shared__ float s_gts[BM];

    int tid = threadIdx.x;
    int wid = tid >> 5, lane = tid & 31;

    if (tid < BM) {
        int r = r0 + tid;
        int t = (r < ne) ? g_tok[e * CAP + r] : -1;
        s_toks[tid] = t;
        s_gts[tid]  = (t >= 0) ? g_gate[t] : 0.f;
    }
    __syncthreads();

    // per-thread load mapping
    int arow = tid >> 1, aseg = tid & 1;                // A: row, 32B segment
    int atok = s_toks[arow];
    const char* axh = (const char*)(g_xh + ((atok >= 0 ? (size_t)atok : 0) * MDIM)) + aseg * 32;
    const char* axl = (const char*)(g_xl + ((atok >= 0 ? (size_t)atok : 0) * MDIM)) + aseg * 32;
    uint32_t abytes = (atok >= 0) ? 16u : 0u;
    uint32_t adst = sb + arow * A_ROWB + aseg * 32;

    int brow = tid >> 3, bcol = (tid & 7) * 2;          // B: k-row, 16B chunk pair
    const char* bwh = (const char*)(g_weh + ((size_t)e << 20) + (size_t)brow * MDIM + n0 + bcol * 8);
    const char* bwl = (const char*)(g_wel + ((size_t)e << 20) + (size_t)brow * MDIM + n0 + bcol * 8);
    uint32_t bdst = sb + brow * B_ROWB + bcol * 16;
    const size_t bkstep = (size_t)BK * MDIM * 2;        // bytes per k-chunk in gmem

    // issue loads for k-chunk kc into stage st
    auto issue = [&](int kc, int st) {
        size_t akoff = (size_t)kc * BK * 2;             // bytes
        uint32_t so = st ? 1u : 0u;
#pragma unroll
        for (int j = 0; j < 2; j++) {
            cp_async16(adst + so * A_TILE + j * 16, axh + akoff + j * 16, abytes);
            cp_async16(adst + OFF_AL + so * A_TILE + j * 16, axl + akoff + j * 16, abytes);
            cp_async16(bdst + OFF_BH + so * B_TILE + j * 16, bwh + (size_t)kc * bkstep + j * 16, 16u);
            cp_async16(bdst + OFF_BL + so * B_TILE + j * 16, bwl + (size_t)kc * bkstep + j * 16, 16u);
        }
        CP_COMMIT();
    };

    int wm = wid & 1, wn = wid >> 1;                    // warp tile: 64m x 32n
    float acc[4][4][4];
#pragma unroll
    for (int a = 0; a < 4; a++)
#pragma unroll
        for (int b = 0; b < 4; b++)
#pragma unroll
            for (int c = 0; c < 4; c++) acc[a][b][c] = 0.f;

    issue(0, 0);

    for (int i = 0; i < NKC; i++) {
        int buf = i & 1;
        if (i + 1 < NKC) issue(i + 1, (i + 1) & 1);
        if (i + 1 < NKC) { CP_WAIT(1); } else { CP_WAIT(0); }
        __syncthreads();

        uint32_t AHs = sb + buf * A_TILE;
        uint32_t ALs = sb + OFF_AL + buf * A_TILE;
        uint32_t BHs = sb + OFF_BH + buf * B_TILE;
        uint32_t BLs = sb + OFF_BL + buf * B_TILE;

#pragma unroll
        for (int ks = 0; ks < 2; ks++) {
            uint32_t ah[4][4], al[4][4], bh[2][4], bl[2][4];
            uint32_t aoff = ks * 32 + 16 * (lane >> 4);
#pragma unroll
            for (int mt = 0; mt < 4; mt++) {
                uint32_t row = wm * 64 + mt * 16 + (lane & 15);
                ldmat_x4(ah[mt], AHs + row * A_ROWB + aoff);
                ldmat_x4(al[mt], ALs + row * A_ROWB + aoff);
            }
            uint32_t brow16 = ks * 16 + (lane & 7) + 8 * ((lane >> 3) & 1);
#pragma unroll
            for (int nh = 0; nh < 2; nh++) {
                uint32_t boff = brow16 * B_ROWB + wn * 64 + nh * 32 + 16 * (lane >> 4);
                ldmat_x4_t(bh[nh], BHs + boff);
                ldmat_x4_t(bl[nh], BLs + boff);
            }
#pragma unroll
            for (int mt = 0; mt < 4; mt++) {
#pragma unroll
                for (int ns = 0; ns < 4; ns++) {
                    uint32_t b0h = bh[ns >> 1][(ns & 1) * 2], b1h = bh[ns >> 1][(ns & 1) * 2 + 1];
                    uint32_t b0l = bl[ns >> 1][(ns & 1) * 2], b1l = bl[ns >> 1][(ns & 1) * 2 + 1];
                    mma16816(acc[mt][ns], ah[mt], b0h, b1h);
                    mma16816(acc[mt][ns], ah[mt], b0l, b1l);
                    mma16816(acc[mt][ns], al[mt], b0h, b1h);
                }
            }
        }
        if (i + 1 < NKC) __syncthreads();
    }

    // epilogue
#pragma unroll
    for (int mt = 0; mt < 4; mt++) {
#pragma unroll
        for (int half = 0; half < 2; half++) {
            int m = wm * 64 + mt * 16 + half * 8 + (lane >> 2);
            if (r0 + m < ne) {
                int   t = s_toks[m];
                float g = s_gts[m];
                float* orow = out + (size_t)t * MDIM + n0 + wn * 32 + (lane & 3) * 2;
#pragma unroll
                for (int ns = 0; ns < 4; ns++) {
                    float2 v;
                    v.x = g * acc[mt][ns][half * 2 + 0];
                    v.y = g * acc[mt][ns][half * 2 + 1];
                    *(float2*)(orow + ns * 8) = v;
                }
            }
        }
    }
}

// ---------------- launcher ----------------
extern "C" void kernel_launch(void* const* d_in, const int* in_sizes, int n_in,
                              void* d_out, int out_size) {
    const float* x  = (const float*)d_in[0];
    const float* wg = (const float*)d_in[1];
    const float* we = (const float*)d_in[2];
    float* out = (float*)d_out;

    cudaMemsetAsync(d_out, 0, sizeof(float) * (size_t)S * MDIM, 0);

    split_x_kernel<<<(S * MDIM / 4) / 256, 256>>>(x);
    split_we_kernel<<<(E * MDIM * MDIM / 4) / 256, 256>>>(we);
    gate_kernel<<<S / 8, 256>>>(x, wg);
    scan_kernel<<<1, 256>>>(out, (long long)out_size);

    cudaFuncSetAttribute(moe_gemm_mma, cudaFuncAttributeMaxDynamicSharedMemorySize, SMEM_BYTES);
    dim3 grid(MDIM / BN, CAP / BM, E);
    moe_gemm_mma<<<grid, 256, SMEM_BYTES>>>(out);
}

// round 5
// speedup vs baseline: 2.5879x; 1.2063x over previous
#include <cuda_runtime.h>
#include <cuda_bf16.h>
#include <stdint.h>

#define S    4096
#define MDIM 1024
#define E    8
#define CAP  1024
#define BM   128
#define BN   256
#define BK   32
#define NKC  (MDIM / BK)   // 32

// ---------------- scratch (device globals; no allocation) ----------------
__device__ int   g_e0[S];
__device__ float g_gate[S];
__device__ float g_me_part[512 * E];
__device__ int   g_tok[E * CAP];
__device__ int   g_ne[E];
__device__ __nv_bfloat16 g_xh[S * MDIM];
__device__ __nv_bfloat16 g_xl[S * MDIM];
__device__ __nv_bfloat16 g_weh[E * MDIM * MDIM];  // [e][k][n], n contiguous
__device__ __nv_bfloat16 g_wel[E * MDIM * MDIM];

__device__ __forceinline__ uint32_t smem_u32(const void* p) {
    uint32_t a;
    asm("{ .reg .u64 t; cvta.to.shared.u64 t, %1; cvt.u32.u64 %0, t; }" : "=r"(a) : "l"(p));
    return a;
}
__device__ __forceinline__ void cp_async16(uint32_t dst, const void* src, uint32_t bytes) {
    asm volatile("cp.async.cg.shared.global [%0], [%1], 16, %2;"
                 :: "r"(dst), "l"(src), "r"(bytes) : "memory");
}
#define CP_COMMIT() asm volatile("cp.async.commit_group;" ::: "memory")
#define CP_WAIT(n)  asm volatile("cp.async.wait_group %0;" :: "n"(n) : "memory")

__device__ __forceinline__ void ldmat_x4(uint32_t* r, uint32_t addr) {
    asm volatile("ldmatrix.sync.aligned.m8n8.x4.shared.b16 {%0,%1,%2,%3}, [%4];"
                 : "=r"(r[0]), "=r"(r[1]), "=r"(r[2]), "=r"(r[3]) : "r"(addr));
}
__device__ __forceinline__ void ldmat_x4_t(uint32_t* r, uint32_t addr) {
    asm volatile("ldmatrix.sync.aligned.m8n8.x4.trans.shared.b16 {%0,%1,%2,%3}, [%4];"
                 : "=r"(r[0]), "=r"(r[1]), "=r"(r[2]), "=r"(r[3]) : "r"(addr));
}
__device__ __forceinline__ void mma16816(float* c, const uint32_t* a, uint32_t b0, uint32_t b1) {
    asm volatile("mma.sync.aligned.m16n8k16.row.col.f32.bf16.bf16.f32 "
                 "{%0,%1,%2,%3}, {%4,%5,%6,%7}, {%8,%9}, {%0,%1,%2,%3};"
                 : "+f"(c[0]), "+f"(c[1]), "+f"(c[2]), "+f"(c[3])
                 : "r"(a[0]), "r"(a[1]), "r"(a[2]), "r"(a[3]), "r"(b0), "r"(b1));
}

// ---------------- kernel 1: gating + fused x split + me partials ----------------
__global__ void __launch_bounds__(256) gate_kernel(const float* __restrict__ x,
                                                   const float* __restrict__ wg) {
    __shared__ float wgs[E * MDIM];
    __shared__ float s_pr[8][E];
    int tid = threadIdx.x;
    for (int i = tid; i < E * MDIM / 4; i += 256)
        ((float4*)wgs)[i] = ((const float4*)wg)[i];
    __syncthreads();

    int warp = tid >> 5, lane = tid & 31;
    int s = blockIdx.x * 8 + warp;
    const float4* xr = (const float4*)(x + (size_t)s * MDIM);
    __nv_bfloat162* xh = (__nv_bfloat162*)(g_xh + (size_t)s * MDIM);
    __nv_bfloat162* xl = (__nv_bfloat162*)(g_xl + (size_t)s * MDIM);
    float acc[E];
#pragma unroll
    for (int e = 0; e < E; e++) acc[e] = 0.f;
#pragma unroll
    for (int it = 0; it < MDIM / 128; it++) {
        int k4 = it * 32 + lane;
        float4 xv = xr[k4];
        // fused split: write bf16 hi/lo
        __nv_bfloat16 h0 = __float2bfloat16(xv.x), h1 = __float2bfloat16(xv.y);
        __nv_bfloat16 h2 = __float2bfloat16(xv.z), h3 = __float2bfloat16(xv.w);
        xh[k4 * 2 + 0] = __halves2bfloat162(h0, h1);
        xh[k4 * 2 + 1] = __halves2bfloat162(h2, h3);
        xl[k4 * 2 + 0] = __halves2bfloat162(__float2bfloat16(xv.x - __bfloat162float(h0)),
                                            __float2bfloat16(xv.y - __bfloat162float(h1)));
        xl[k4 * 2 + 1] = __halves2bfloat162(__float2bfloat16(xv.z - __bfloat162float(h2)),
                                            __float2bfloat16(xv.w - __bfloat162float(h3)));
#pragma unroll
        for (int e = 0; e < E; e++) {
            float4 wv = ((const float4*)(wgs + e * MDIM))[k4];
            acc[e] += xv.x * wv.x + xv.y * wv.y + xv.z * wv.z + xv.w * wv.w;
        }
    }
#pragma unroll
    for (int e = 0; e < E; e++) {
#pragma unroll
        for (int off = 16; off; off >>= 1)
            acc[e] += __shfl_xor_sync(0xffffffffu, acc[e], off);
    }
    if (lane == 0) {
        float mx = acc[0]; int ei = 0;
#pragma unroll
        for (int e = 1; e < E; e++) if (acc[e] > mx) { mx = acc[e]; ei = e; }
        float ex[E]; float sum = 0.f;
#pragma unroll
        for (int e = 0; e < E; e++) { ex[e] = expf(acc[e] - mx); sum += ex[e]; }
        float inv = 1.f / sum;
#pragma unroll
        for (int e = 0; e < E; e++) s_pr[warp][e] = ex[e] * inv;
        g_e0[s]   = ei;
        g_gate[s] = ex[ei] * inv;
    }
    __syncthreads();
    if (tid < E) {
        float m = 0.f;
#pragma unroll
        for (int w = 0; w < 8; w++) m += s_pr[w][tid];
        g_me_part[blockIdx.x * E + tid] = m;
    }
}

// ---------------- kernel 2: ordered prefix scan + loss ----------------
__global__ void __launch_bounds__(256) scan_kernel(float* __restrict__ d_out,
                                                   long long out_size) {
    const int T = 256, CH = S / T;  // 16
    __shared__ int   cnt[T][E];
    __shared__ float s_me[32][E];
    __shared__ int   tot[E];
    int tid = threadIdx.x;

    // local e0 (vectorized int4)
    int e0l[CH];
    {
        const int4* p = (const int4*)(g_e0 + tid * CH);
#pragma unroll
        for (int q = 0; q < CH / 4; q++) {
            int4 v = p[q];
            e0l[q * 4 + 0] = v.x; e0l[q * 4 + 1] = v.y;
            e0l[q * 4 + 2] = v.z; e0l[q * 4 + 3] = v.w;
        }
    }
    int c[E];
#pragma unroll
    for (int e = 0; e < E; e++) c[e] = 0;
#pragma unroll
    for (int i = 0; i < CH; i++) c[e0l[i]]++;
#pragma unroll
    for (int e = 0; e < E; e++) cnt[tid][e] = c[e];

    // me: reduce 512x8 partials deterministically (fixed-order sums)
    {
        int e = tid & 7, grp = tid >> 3;  // 32 groups
        float m = 0.f;
#pragma unroll
        for (int j = 0; j < 16; j++) m += g_me_part[(grp * 16 + j) * E + e];
        s_me[grp][e] = m;
    }
    __syncthreads();
    for (int stride = 16; stride; stride >>= 1) {
        if (tid < stride * E) {
            int e = tid & 7, grp = tid >> 3;
            s_me[grp][e] += s_me[grp + stride][e];
        }
        __syncthreads();
    }

    if (tid < E) {
        int run = 0;
        for (int t = 0; t < T; t++) { int v = cnt[t][tid]; cnt[t][tid] = run; run += v; }
        tot[tid] = run;
        g_ne[tid] = run < CAP ? run : CAP;
    }
    __syncthreads();
    int off[E];
#pragma unroll
    for (int e = 0; e < E; e++) off[e] = cnt[tid][e];
    int base_s = tid * CH;
#pragma unroll
    for (int i = 0; i < CH; i++) {
        int e = e0l[i];
        int loc = off[e]++;
        if (loc < CAP) g_tok[e * CAP + loc] = base_s + i;
    }
    if (tid == 0 && out_size > (long long)S * MDIM) {
        float loss = 0.f;
#pragma unroll
        for (int e = 0; e < E; e++) loss += s_me[0][e] * (float)tot[e];
        loss *= (float)E / ((float)S * (float)S);
        d_out[(long long)S * MDIM] = loss;
    }
}

// ---------------- prep: we fp32 -> bf16 hi/lo ----------------
__global__ void __launch_bounds__(256) split_we_kernel(const float* __restrict__ we) {
    size_t i = (size_t)blockIdx.x * 256 + threadIdx.x;
    float4 v = ((const float4*)we)[i];
    __nv_bfloat16 h0 = __float2bfloat16(v.x), h1 = __float2bfloat16(v.y);
    __nv_bfloat16 h2 = __float2bfloat16(v.z), h3 = __float2bfloat16(v.w);
    __nv_bfloat162* oh = (__nv_bfloat162*)g_weh + i * 2;
    __nv_bfloat162* ol = (__nv_bfloat162*)g_wel + i * 2;
    oh[0] = __halves2bfloat162(h0, h1);
    oh[1] = __halves2bfloat162(h2, h3);
    ol[0] = __halves2bfloat162(__float2bfloat16(v.x - __bfloat162float(h0)),
                               __float2bfloat16(v.y - __bfloat162float(h1)));
    ol[1] = __halves2bfloat162(__float2bfloat16(v.z - __bfloat162float(h2)),
                               __float2bfloat16(v.w - __bfloat162float(h3)));
}

// ---------------- kernel 3: grouped GEMM, 128x256x32, 512 threads ----------------
#define A_ROWB 80
#define B_ROWB 528
#define A_TILE (BM * A_ROWB)            // 10240
#define B_TILE (BK * B_ROWB)            // 16896
#define OFF_AL (2 * A_TILE)             // 20480
#define OFF_BH (4 * A_TILE)             // 40960
#define OFF_BL (4 * A_TILE + 2 * B_TILE)// 74752
#define SMEM_BYTES (4 * A_TILE + 4 * B_TILE)  // 108544

__global__ void __launch_bounds__(512) moe_gemm_mma(float* __restrict__ out) {
    int e  = blockIdx.z;
    int ne = g_ne[e];
    int r0 = blockIdx.y * BM;
    if (r0 >= ne) return;
    int n0 = blockIdx.x * BN;

    extern __shared__ __align__(16) char sm[];
    uint32_t sb = smem_u32(sm);
    __shared__ int   s_toks[BM];
    __shared__ float s_gts[BM];

    int tid = threadIdx.x;
    int wid = tid >> 5, lane = tid & 31;

    if (tid < BM) {
        int r = r0 + tid;
        int t = (r < ne) ? g_tok[e * CAP + r] : -1;
        s_toks[tid] = t;
        s_gts[tid]  = (t >= 0) ? g_gate[t] : 0.f;
    }
    __syncthreads();

    // A load: 128 rows x 64B, 4 chunks/row; thread -> (row=tid>>2, seg=tid&3)
    int arow = tid >> 2, aseg = tid & 3;
    int atok = s_toks[arow];
    const char* axh = (const char*)(g_xh + ((atok >= 0 ? (size_t)atok : 0) * MDIM)) + aseg * 16;
    const char* axl = (const char*)(g_xl + ((atok >= 0 ? (size_t)atok : 0) * MDIM)) + aseg * 16;
    uint32_t abytes = (atok >= 0) ? 16u : 0u;
    uint32_t adst = sb + arow * A_ROWB + aseg * 16;

    // B load: 32 rows x 512B, 32 chunks/row; thread -> (row=tid>>4, 2 chunks)
    int brow = tid >> 4, bc = tid & 15;
    const char* bwh = (const char*)(g_weh + ((size_t)e << 20) + (size_t)brow * MDIM + n0) + bc * 16;
    const char* bwl = (const char*)(g_wel + ((size_t)e << 20) + (size_t)brow * MDIM + n0) + bc * 16;
    uint32_t bdst = sb + brow * B_ROWB + bc * 16;
    const size_t bkstep = (size_t)BK * MDIM * 2;  // bytes per k-chunk

    auto issue = [&](int kc, int st) {
        size_t akoff = (size_t)kc * BK * 2;
        uint32_t so = st ? 1u : 0u;
        cp_async16(adst + so * A_TILE, axh + akoff, abytes);
        cp_async16(adst + OFF_AL + so * A_TILE, axl + akoff, abytes);
        size_t bko = (size_t)kc * bkstep;
#pragma unroll
        for (int j = 0; j < 2; j++) {
            cp_async16(bdst + OFF_BH + so * B_TILE + j * 256, bwh + bko + j * 256, 16u);
            cp_async16(bdst + OFF_BL + so * B_TILE + j * 256, bwl + bko + j * 256, 16u);
        }
        CP_COMMIT();
    };

    int wm = wid & 3, wn = wid >> 2;   // warp tile 32m x 64n
    float acc[2][8][4];
#pragma unroll
    for (int a = 0; a < 2; a++)
#pragma unroll
        for (int b = 0; b < 8; b++)
#pragma unroll
            for (int c2 = 0; c2 < 4; c2++) acc[a][b][c2] = 0.f;

    issue(0, 0);

    for (int i = 0; i < NKC; i++) {
        int buf = i & 1;
        if (i + 1 < NKC) issue(i + 1, (i + 1) & 1);
        if (i + 1 < NKC) { CP_WAIT(1); } else { CP_WAIT(0); }
        __syncthreads();

        uint32_t AHs = sb + buf * A_TILE;
        uint32_t ALs = sb + OFF_AL + buf * A_TILE;
        uint32_t BHs = sb + OFF_BH + buf * B_TILE;
        uint32_t BLs = sb + OFF_BL + buf * B_TILE;

#pragma unroll
        for (int ks = 0; ks < 2; ks++) {
            uint32_t ah[2][4], al[2][4], bh[4][4], bl[4][4];
            uint32_t aoff = ks * 32 + 16 * (lane >> 4);
#pragma unroll
            for (int mt = 0; mt < 2; mt++) {
                uint32_t row = wm * 32 + mt * 16 + (lane & 15);
                ldmat_x4(ah[mt], AHs + row * A_ROWB + aoff);
                ldmat_x4(al[mt], ALs + row * A_ROWB + aoff);
            }
            uint32_t brow16 = ks * 16 + (lane & 7) + 8 * ((lane >> 3) & 1);
#pragma unroll
            for (int nh = 0; nh < 4; nh++) {
                uint32_t boff = brow16 * B_ROWB + wn * 128 + nh * 32 + 16 * (lane >> 4);
                ldmat_x4_t(bh[nh], BHs + boff);
                ldmat_x4_t(bl[nh], BLs + boff);
            }
#pragma unroll
            for (int mt = 0; mt < 2; mt++) {
#pragma unroll
                for (int ns = 0; ns < 8; ns++) {
                    uint32_t b0h = bh[ns >> 1][(ns & 1) * 2], b1h = bh[ns >> 1][(ns & 1) * 2 + 1];
                    uint32_t b0l = bl[ns >> 1][(ns & 1) * 2], b1l = bl[ns >> 1][(ns & 1) * 2 + 1];
                    mma16816(acc[mt][ns], ah[mt], b0h, b1h);
                    mma16816(acc[mt][ns], ah[mt], b0l, b1l);
                    mma16816(acc[mt][ns], al[mt], b0h, b1h);
                }
            }
        }
        if (i + 1 < NKC) __syncthreads();
    }

    // epilogue
#pragma unroll
    for (int mt = 0; mt < 2; mt++) {
#pragma unroll
        for (int half = 0; half < 2; half++) {
            int m = wm * 32 + mt * 16 + half * 8 + (lane >> 2);
            if (r0 + m < ne) {
                int   t = s_toks[m];
                float g = s_gts[m];
                float* orow = out + (size_t)t * MDIM + n0 + wn * 64 + (lane & 3) * 2;
#pragma unroll
                for (int ns = 0; ns < 8; ns++) {
                    float2 v;
                    v.x = g * acc[mt][ns][half * 2 + 0];
                    v.y = g * acc[mt][ns][half * 2 + 1];
                    *(float2*)(orow + ns * 8) = v;
                }
            }
        }
    }
}

// ---------------- launcher ----------------
extern "C" void kernel_launch(void* const* d_in, const int* in_sizes, int n_in,
                              void* d_out, int out_size) {
    const float* x  = (const float*)d_in[0];
    const float* wg = (const float*)d_in[1];
    const float* we = (const float*)d_in[2];
    float* out = (float*)d_out;

    cudaMemsetAsync(d_out, 0, sizeof(float) * (size_t)S * MDIM, 0);

    split_we_kernel<<<(E * MDIM * MDIM / 4) / 256, 256>>>(we);
    gate_kernel<<<S / 8, 256>>>(x, wg);
    scan_kernel<<<1, 256>>>(out, (long long)out_size);

    cudaFuncSetAttribute(moe_gemm_mma, cudaFuncAttributeMaxDynamicSharedMemorySize, SMEM_BYTES);
    dim3 grid(MDIM / BN, CAP / BM, E);
    moe_gemm_mma<<<grid, 512, SMEM_BYTES>>>(out);
}

// round 6
// speedup vs baseline: 2.6652x; 1.0299x over previous
#include <cuda_runtime.h>
#include <cuda_bf16.h>
#include <stdint.h>

#define S    4096
#define MDIM 1024
#define E    8
#define CAP  1024
#define BM   128
#define BN   256
#define BK   32
#define NKC  (MDIM / BK)   // 32

// ---------------- scratch (device globals; no allocation) ----------------
__device__ int   g_e0[S];
__device__ float g_gate[S];
__device__ float g_me_part[512 * E];
__device__ int   g_tok[E * CAP];
__device__ int   g_ne[E];
__device__ __nv_bfloat16 g_xh[S * MDIM];
__device__ __nv_bfloat16 g_xl[S * MDIM];
__device__ __nv_bfloat16 g_weh[E * MDIM * MDIM];  // [e][k][n], n contiguous
__device__ __nv_bfloat16 g_wel[E * MDIM * MDIM];

__device__ __forceinline__ uint32_t smem_u32(const void* p) {
    uint32_t a;
    asm("{ .reg .u64 t; cvta.to.shared.u64 t, %1; cvt.u32.u64 %0, t; }" : "=r"(a) : "l"(p));
    return a;
}
__device__ __forceinline__ void cp_async16(uint32_t dst, const void* src, uint32_t bytes) {
    asm volatile("cp.async.cg.shared.global [%0], [%1], 16, %2;"
                 :: "r"(dst), "l"(src), "r"(bytes) : "memory");
}
#define CP_COMMIT() asm volatile("cp.async.commit_group;" ::: "memory")
#define CP_WAIT(n)  asm volatile("cp.async.wait_group %0;" :: "n"(n) : "memory")

__device__ __forceinline__ void ldmat_x4(uint32_t* r, uint32_t addr) {
    asm volatile("ldmatrix.sync.aligned.m8n8.x4.shared.b16 {%0,%1,%2,%3}, [%4];"
                 : "=r"(r[0]), "=r"(r[1]), "=r"(r[2]), "=r"(r[3]) : "r"(addr));
}
__device__ __forceinline__ void ldmat_x4_t(uint32_t* r, uint32_t addr) {
    asm volatile("ldmatrix.sync.aligned.m8n8.x4.trans.shared.b16 {%0,%1,%2,%3}, [%4];"
                 : "=r"(r[0]), "=r"(r[1]), "=r"(r[2]), "=r"(r[3]) : "r"(addr));
}
__device__ __forceinline__ void mma16816(float* c, const uint32_t* a, uint32_t b0, uint32_t b1) {
    asm volatile("mma.sync.aligned.m16n8k16.row.col.f32.bf16.bf16.f32 "
                 "{%0,%1,%2,%3}, {%4,%5,%6,%7}, {%8,%9}, {%0,%1,%2,%3};"
                 : "+f"(c[0]), "+f"(c[1]), "+f"(c[2]), "+f"(c[3])
                 : "r"(a[0]), "r"(a[1]), "r"(a[2]), "r"(a[3]), "r"(b0), "r"(b1));
}

// ---------------- kernel 1: gating + fused x split + me partials ----------------
__global__ void __launch_bounds__(256) gate_kernel(const float* __restrict__ x,
                                                   const float* __restrict__ wg) {
    __shared__ float wgs[E * MDIM];
    __shared__ float s_pr[8][E];
    int tid = threadIdx.x;
    for (int i = tid; i < E * MDIM / 4; i += 256)
        ((float4*)wgs)[i] = ((const float4*)wg)[i];
    __syncthreads();

    int warp = tid >> 5, lane = tid & 31;
    int s = blockIdx.x * 8 + warp;
    const float4* xr = (const float4*)(x + (size_t)s * MDIM);
    __nv_bfloat162* xh = (__nv_bfloat162*)(g_xh + (size_t)s * MDIM);
    __nv_bfloat162* xl = (__nv_bfloat162*)(g_xl + (size_t)s * MDIM);
    float acc[E];
#pragma unroll
    for (int e = 0; e < E; e++) acc[e] = 0.f;
#pragma unroll
    for (int it = 0; it < MDIM / 128; it++) {
        int k4 = it * 32 + lane;
        float4 xv = xr[k4];
        __nv_bfloat16 h0 = __float2bfloat16(xv.x), h1 = __float2bfloat16(xv.y);
        __nv_bfloat16 h2 = __float2bfloat16(xv.z), h3 = __float2bfloat16(xv.w);
        xh[k4 * 2 + 0] = __halves2bfloat162(h0, h1);
        xh[k4 * 2 + 1] = __halves2bfloat162(h2, h3);
        xl[k4 * 2 + 0] = __halves2bfloat162(__float2bfloat16(xv.x - __bfloat162float(h0)),
                                            __float2bfloat16(xv.y - __bfloat162float(h1)));
        xl[k4 * 2 + 1] = __halves2bfloat162(__float2bfloat16(xv.z - __bfloat162float(h2)),
                                            __float2bfloat16(xv.w - __bfloat162float(h3)));
#pragma unroll
        for (int e = 0; e < E; e++) {
            float4 wv = ((const float4*)(wgs + e * MDIM))[k4];
            acc[e] += xv.x * wv.x + xv.y * wv.y + xv.z * wv.z + xv.w * wv.w;
        }
    }
#pragma unroll
    for (int e = 0; e < E; e++) {
#pragma unroll
        for (int off = 16; off; off >>= 1)
            acc[e] += __shfl_xor_sync(0xffffffffu, acc[e], off);
    }
    if (lane == 0) {
        float mx = acc[0]; int ei = 0;
#pragma unroll
        for (int e = 1; e < E; e++) if (acc[e] > mx) { mx = acc[e]; ei = e; }
        float ex[E]; float sum = 0.f;
#pragma unroll
        for (int e = 0; e < E; e++) { ex[e] = expf(acc[e] - mx); sum += ex[e]; }
        float inv = 1.f / sum;
#pragma unroll
        for (int e = 0; e < E; e++) s_pr[warp][e] = ex[e] * inv;
        g_e0[s]   = ei;
        g_gate[s] = ex[ei] * inv;
    }
    __syncthreads();
    if (tid < E) {
        float m = 0.f;
#pragma unroll
        for (int w = 0; w < 8; w++) m += s_pr[w][tid];
        g_me_part[blockIdx.x * E + tid] = m;
    }
}

// ---------------- kernel 2: ordered prefix scan + loss ----------------
__global__ void __launch_bounds__(256) scan_kernel(float* __restrict__ d_out,
                                                   long long out_size) {
    const int T = 256, CH = S / T;  // 16
    __shared__ int   cnt[T][E];
    __shared__ float s_me[32][E];
    __shared__ int   tot[E];
    int tid = threadIdx.x;

    int e0l[CH];
    {
        const int4* p = (const int4*)(g_e0 + tid * CH);
#pragma unroll
        for (int q = 0; q < CH / 4; q++) {
            int4 v = p[q];
            e0l[q * 4 + 0] = v.x; e0l[q * 4 + 1] = v.y;
            e0l[q * 4 + 2] = v.z; e0l[q * 4 + 3] = v.w;
        }
    }
    int c[E];
#pragma unroll
    for (int e = 0; e < E; e++) c[e] = 0;
#pragma unroll
    for (int i = 0; i < CH; i++) c[e0l[i]]++;
#pragma unroll
    for (int e = 0; e < E; e++) cnt[tid][e] = c[e];

    {
        int e = tid & 7, grp = tid >> 3;
        float m = 0.f;
#pragma unroll
        for (int j = 0; j < 16; j++) m += g_me_part[(grp * 16 + j) * E + e];
        s_me[grp][e] = m;
    }
    __syncthreads();
    for (int stride = 16; stride; stride >>= 1) {
        if (tid < stride * E) {
            int e = tid & 7, grp = tid >> 3;
            s_me[grp][e] += s_me[grp + stride][e];
        }
        __syncthreads();
    }

    if (tid < E) {
        int run = 0;
        for (int t = 0; t < T; t++) { int v = cnt[t][tid]; cnt[t][tid] = run; run += v; }
        tot[tid] = run;
        g_ne[tid] = run < CAP ? run : CAP;
    }
    __syncthreads();
    int off[E];
#pragma unroll
    for (int e = 0; e < E; e++) off[e] = cnt[tid][e];
    int base_s = tid * CH;
#pragma unroll
    for (int i = 0; i < CH; i++) {
        int e = e0l[i];
        int loc = off[e]++;
        if (loc < CAP) g_tok[e * CAP + loc] = base_s + i;
    }
    if (tid == 0 && out_size > (long long)S * MDIM) {
        float loss = 0.f;
#pragma unroll
        for (int e = 0; e < E; e++) loss += s_me[0][e] * (float)tot[e];
        loss *= (float)E / ((float)S * (float)S);
        d_out[(long long)S * MDIM] = loss;
    }
}

// ---------------- prep: we fp32 -> bf16 hi/lo ----------------
__global__ void __launch_bounds__(256) split_we_kernel(const float* __restrict__ we) {
    size_t i = (size_t)blockIdx.x * 256 + threadIdx.x;
    float4 v = ((const float4*)we)[i];
    __nv_bfloat16 h0 = __float2bfloat16(v.x), h1 = __float2bfloat16(v.y);
    __nv_bfloat16 h2 = __float2bfloat16(v.z), h3 = __float2bfloat16(v.w);
    __nv_bfloat162* oh = (__nv_bfloat162*)g_weh + i * 2;
    __nv_bfloat162* ol = (__nv_bfloat162*)g_wel + i * 2;
    oh[0] = __halves2bfloat162(h0, h1);
    oh[1] = __halves2bfloat162(h2, h3);
    ol[0] = __halves2bfloat162(__float2bfloat16(v.x - __bfloat162float(h0)),
                               __float2bfloat16(v.y - __bfloat162float(h1)));
    ol[1] = __halves2bfloat162(__float2bfloat16(v.z - __bfloat162float(h2)),
                               __float2bfloat16(v.w - __bfloat162float(h3)));
}

// ---------------- kernel 3: grouped GEMM, 128x256x32, 3-stage, 1 sync/iter ----------------
#define A_ROWB 80
#define B_ROWB 528
#define A_TILE (BM * A_ROWB)            // 10240
#define B_TILE (BK * B_ROWB)            // 16896
#define STG_AH 0
#define STG_AL (A_TILE)
#define STG_BH (2 * A_TILE)
#define STG_BL (2 * A_TILE + B_TILE)
#define STG_SZ (2 * A_TILE + 2 * B_TILE)   // 54272
#define STAGES 3
#define SMEM_BYTES (STAGES * STG_SZ)        // 162816

__global__ void __launch_bounds__(512) moe_gemm_mma(float* __restrict__ out) {
    int e  = blockIdx.z;
    int ne = g_ne[e];
    int r0 = blockIdx.y * BM;
    if (r0 >= ne) return;
    int n0 = blockIdx.x * BN;

    extern __shared__ __align__(16) char sm[];
    uint32_t sb = smem_u32(sm);
    __shared__ int   s_toks[BM];
    __shared__ float s_gts[BM];

    int tid = threadIdx.x;
    int wid = tid >> 5, lane = tid & 31;

    if (tid < BM) {
        int r = r0 + tid;
        int t = (r < ne) ? g_tok[e * CAP + r] : -1;
        s_toks[tid] = t;
        s_gts[tid]  = (t >= 0) ? g_gate[t] : 0.f;
    }
    __syncthreads();

    // A load: 128 rows x 64B; thread -> (row=tid>>2, seg=tid&3)
    int arow = tid >> 2, aseg = tid & 3;
    int atok = s_toks[arow];
    const char* axh = (const char*)(g_xh + ((atok >= 0 ? (size_t)atok : 0) * MDIM)) + aseg * 16;
    const char* axl = (const char*)(g_xl + ((atok >= 0 ? (size_t)atok : 0) * MDIM)) + aseg * 16;
    uint32_t abytes = (atok >= 0) ? 16u : 0u;
    uint32_t adst = arow * A_ROWB + aseg * 16;

    // B load: 32 rows x 512B; thread -> (row=tid>>4, 2 chunks of 16B, 256B apart)
    int brow = tid >> 4, bc = tid & 15;
    const char* bwh = (const char*)(g_weh + ((size_t)e << 20) + (size_t)brow * MDIM + n0) + bc * 16;
    const char* bwl = (const char*)(g_wel + ((size_t)e << 20) + (size_t)brow * MDIM + n0) + bc * 16;
    uint32_t bdst = brow * B_ROWB + bc * 16;
    const size_t bkstep = (size_t)BK * MDIM * 2;

    auto issue = [&](int kc, int st) {
        uint32_t so = sb + st * STG_SZ;
        size_t akoff = (size_t)kc * BK * 2;
        cp_async16(so + STG_AH + adst, axh + akoff, abytes);
        cp_async16(so + STG_AL + adst, axl + akoff, abytes);
        size_t bko = (size_t)kc * bkstep;
#pragma unroll
        for (int j = 0; j < 2; j++) {
            cp_async16(so + STG_BH + bdst + j * 256, bwh + bko + j * 256, 16u);
            cp_async16(so + STG_BL + bdst + j * 256, bwl + bko + j * 256, 16u);
        }
        CP_COMMIT();
    };

    int wm = wid & 3, wn = wid >> 2;   // warp tile 32m x 64n
    float acc[2][8][4];
#pragma unroll
    for (int a = 0; a < 2; a++)
#pragma unroll
        for (int b = 0; b < 8; b++)
#pragma unroll
            for (int c2 = 0; c2 < 4; c2++) acc[a][b][c2] = 0.f;

    issue(0, 0);
    issue(1, 1);

    int st = 0;
    for (int i = 0; i < NKC; i++) {
        if (i + 1 < NKC) { CP_WAIT(1); } else { CP_WAIT(0); }
        __syncthreads();
        if (i + 2 < NKC) {
            int nst = st + 2; if (nst >= STAGES) nst -= STAGES;
            issue(i + 2, nst);
        }

        uint32_t so  = sb + st * STG_SZ;
        uint32_t AHs = so + STG_AH;
        uint32_t ALs = so + STG_AL;
        uint32_t BHs = so + STG_BH;
        uint32_t BLs = so + STG_BL;

#pragma unroll
        for (int ks = 0; ks < 2; ks++) {
            uint32_t ah[2][4], al[2][4], bh[4][4], bl[4][4];
            uint32_t aoff = ks * 32 + 16 * (lane >> 4);
#pragma unroll
            for (int mt = 0; mt < 2; mt++) {
                uint32_t row = wm * 32 + mt * 16 + (lane & 15);
                ldmat_x4(ah[mt], AHs + row * A_ROWB + aoff);
                ldmat_x4(al[mt], ALs + row * A_ROWB + aoff);
            }
            uint32_t brow16 = ks * 16 + (lane & 7) + 8 * ((lane >> 3) & 1);
#pragma unroll
            for (int nh = 0; nh < 4; nh++) {
                uint32_t boff = brow16 * B_ROWB + wn * 128 + nh * 32 + 16 * (lane >> 4);
                ldmat_x4_t(bh[nh], BHs + boff);
                ldmat_x4_t(bl[nh], BLs + boff);
            }
#pragma unroll
            for (int mt = 0; mt < 2; mt++) {
#pragma unroll
                for (int ns = 0; ns < 8; ns++) {
                    uint32_t b0h = bh[ns >> 1][(ns & 1) * 2], b1h = bh[ns >> 1][(ns & 1) * 2 + 1];
                    uint32_t b0l = bl[ns >> 1][(ns & 1) * 2], b1l = bl[ns >> 1][(ns & 1) * 2 + 1];
                    mma16816(acc[mt][ns], ah[mt], b0h, b1h);
                    mma16816(acc[mt][ns], ah[mt], b0l, b1l);
                    mma16816(acc[mt][ns], al[mt], b0h, b1h);
                }
            }
        }
        st++; if (st >= STAGES) st = 0;
    }

    // epilogue
#pragma unroll
    for (int mt = 0; mt < 2; mt++) {
#pragma unroll
        for (int half = 0; half < 2; half++) {
            int m = wm * 32 + mt * 16 + half * 8 + (lane >> 2);
            if (r0 + m < ne) {
                int   t = s_toks[m];
                float g = s_gts[m];
                float* orow = out + (size_t)t * MDIM + n0 + wn * 64 + (lane & 3) * 2;
#pragma unroll
                for (int ns = 0; ns < 8; ns++) {
                    float2 v;
                    v.x = g * acc[mt][ns][half * 2 + 0];
                    v.y = g * acc[mt][ns][half * 2 + 1];
                    *(float2*)(orow + ns * 8) = v;
                }
            }
        }
    }
}

// ---------------- launcher ----------------
extern "C" void kernel_launch(void* const* d_in, const int* in_sizes, int n_in,
                              void* d_out, int out_size) {
    const float* x  = (const float*)d_in[0];
    const float* wg = (const float*)d_in[1];
    const float* we = (const float*)d_in[2];
    float* out = (float*)d_out;

    cudaMemsetAsync(d_out, 0, sizeof(float) * (size_t)S * MDIM, 0);

    split_we_kernel<<<(E * MDIM * MDIM / 4) / 256, 256>>>(we);
    gate_kernel<<<S / 8, 256>>>(x, wg);
    scan_kernel<<<1, 256>>>(out, (long long)out_size);

    cudaFuncSetAttribute(moe_gemm_mma, cudaFuncAttributeMaxDynamicSharedMemorySize, SMEM_BYTES);
    dim3 grid(MDIM / BN, CAP / BM, E);
    moe_gemm_mma<<<grid, 512, SMEM_BYTES>>>(out);
}

// round 7
// speedup vs baseline: 3.3986x; 1.2752x over previous
#include <cuda_runtime.h>
#include <cuda_fp16.h>
#include <stdint.h>

#define S    4096
#define MDIM 1024
#define E    8
#define CAP  1024
#define BM   128
#define BN   256
#define BK   32
#define NKC  (MDIM / BK)   // 32

// ---------------- scratch (device globals; no allocation) ----------------
__device__ int    g_e0[S];
__device__ float  g_gate[S];
__device__ float  g_me_part[512 * E];
__device__ int    g_tok[E * CAP];
__device__ int    g_ne[E];
__device__ __half g_xh[S * MDIM];                 // x rounded to fp16
__device__ __half g_weh[E * MDIM * MDIM];         // we hi (fp16), [e][k][n]
__device__ __half g_wel[E * MDIM * MDIM];         // we lo (fp16)

__device__ __forceinline__ uint32_t smem_u32(const void* p) {
    uint32_t a;
    asm("{ .reg .u64 t; cvta.to.shared.u64 t, %1; cvt.u32.u64 %0, t; }" : "=r"(a) : "l"(p));
    return a;
}
__device__ __forceinline__ void cp_async16(uint32_t dst, const void* src, uint32_t bytes) {
    asm volatile("cp.async.cg.shared.global [%0], [%1], 16, %2;"
                 :: "r"(dst), "l"(src), "r"(bytes) : "memory");
}
#define CP_COMMIT() asm volatile("cp.async.commit_group;" ::: "memory")
#define CP_WAIT(n)  asm volatile("cp.async.wait_group %0;" :: "n"(n) : "memory")

__device__ __forceinline__ void ldmat_x4(uint32_t* r, uint32_t addr) {
    asm volatile("ldmatrix.sync.aligned.m8n8.x4.shared.b16 {%0,%1,%2,%3}, [%4];"
                 : "=r"(r[0]), "=r"(r[1]), "=r"(r[2]), "=r"(r[3]) : "r"(addr));
}
__device__ __forceinline__ void ldmat_x4_t(uint32_t* r, uint32_t addr) {
    asm volatile("ldmatrix.sync.aligned.m8n8.x4.trans.shared.b16 {%0,%1,%2,%3}, [%4];"
                 : "=r"(r[0]), "=r"(r[1]), "=r"(r[2]), "=r"(r[3]) : "r"(addr));
}
__device__ __forceinline__ void mma16816(float* c, const uint32_t* a, uint32_t b0, uint32_t b1) {
    asm volatile("mma.sync.aligned.m16n8k16.row.col.f32.f16.f16.f32 "
                 "{%0,%1,%2,%3}, {%4,%5,%6,%7}, {%8,%9}, {%0,%1,%2,%3};"
                 : "+f"(c[0]), "+f"(c[1]), "+f"(c[2]), "+f"(c[3])
                 : "r"(a[0]), "r"(a[1]), "r"(a[2]), "r"(a[3]), "r"(b0), "r"(b1));
}

// ---------------- kernel 1: gating + fused x->fp16 + me partials ----------------
__global__ void __launch_bounds__(256) gate_kernel(const float* __restrict__ x,
                                                   const float* __restrict__ wg) {
    __shared__ float wgs[E * MDIM];
    __shared__ float s_pr[8][E];
    int tid = threadIdx.x;
    for (int i = tid; i < E * MDIM / 4; i += 256)
        ((float4*)wgs)[i] = ((const float4*)wg)[i];
    __syncthreads();

    int warp = tid >> 5, lane = tid & 31;
    int s = blockIdx.x * 8 + warp;
    const float4* xr = (const float4*)(x + (size_t)s * MDIM);
    __half2* xh = (__half2*)(g_xh + (size_t)s * MDIM);
    float acc[E];
#pragma unroll
    for (int e = 0; e < E; e++) acc[e] = 0.f;
#pragma unroll
    for (int it = 0; it < MDIM / 128; it++) {
        int k4 = it * 32 + lane;
        float4 xv = xr[k4];
        xh[k4 * 2 + 0] = __halves2half2(__float2half_rn(xv.x), __float2half_rn(xv.y));
        xh[k4 * 2 + 1] = __halves2half2(__float2half_rn(xv.z), __float2half_rn(xv.w));
#pragma unroll
        for (int e = 0; e < E; e++) {
            float4 wv = ((const float4*)(wgs + e * MDIM))[k4];
            acc[e] += xv.x * wv.x + xv.y * wv.y + xv.z * wv.z + xv.w * wv.w;
        }
    }
#pragma unroll
    for (int e = 0; e < E; e++) {
#pragma unroll
        for (int off = 16; off; off >>= 1)
            acc[e] += __shfl_xor_sync(0xffffffffu, acc[e], off);
    }
    if (lane == 0) {
        float mx = acc[0]; int ei = 0;
#pragma unroll
        for (int e = 1; e < E; e++) if (acc[e] > mx) { mx = acc[e]; ei = e; }
        float ex[E]; float sum = 0.f;
#pragma unroll
        for (int e = 0; e < E; e++) { ex[e] = expf(acc[e] - mx); sum += ex[e]; }
        float inv = 1.f / sum;
#pragma unroll
        for (int e = 0; e < E; e++) s_pr[warp][e] = ex[e] * inv;
        g_e0[s]   = ei;
        g_gate[s] = ex[ei] * inv;
    }
    __syncthreads();
    if (tid < E) {
        float m = 0.f;
#pragma unroll
        for (int w = 0; w < 8; w++) m += s_pr[w][tid];
        g_me_part[blockIdx.x * E + tid] = m;
    }
}

// ---------------- kernel 2: ordered prefix scan + loss ----------------
__global__ void __launch_bounds__(256) scan_kernel(float* __restrict__ d_out,
                                                   long long out_size) {
    const int T = 256, CH = S / T;  // 16
    __shared__ int   cnt[T][E];
    __shared__ float s_me[32][E];
    __shared__ int   tot[E];
    int tid = threadIdx.x;

    int e0l[CH];
    {
        const int4* p = (const int4*)(g_e0 + tid * CH);
#pragma unroll
        for (int q = 0; q < CH / 4; q++) {
            int4 v = p[q];
            e0l[q * 4 + 0] = v.x; e0l[q * 4 + 1] = v.y;
            e0l[q * 4 + 2] = v.z; e0l[q * 4 + 3] = v.w;
        }
    }
    int c[E];
#pragma unroll
    for (int e = 0; e < E; e++) c[e] = 0;
#pragma unroll
    for (int i = 0; i < CH; i++) c[e0l[i]]++;
#pragma unroll
    for (int e = 0; e < E; e++) cnt[tid][e] = c[e];

    {
        int e = tid & 7, grp = tid >> 3;
        float m = 0.f;
#pragma unroll
        for (int j = 0; j < 16; j++) m += g_me_part[(grp * 16 + j) * E + e];
        s_me[grp][e] = m;
    }
    __syncthreads();
    for (int stride = 16; stride; stride >>= 1) {
        if (tid < stride * E) {
            int e = tid & 7, grp = tid >> 3;
            s_me[grp][e] += s_me[grp + stride][e];
        }
        __syncthreads();
    }

    if (tid < E) {
        int run = 0;
        for (int t = 0; t < T; t++) { int v = cnt[t][tid]; cnt[t][tid] = run; run += v; }
        tot[tid] = run;
        g_ne[tid] = run < CAP ? run : CAP;
    }
    __syncthreads();
    int off[E];
#pragma unroll
    for (int e = 0; e < E; e++) off[e] = cnt[tid][e];
    int base_s = tid * CH;
#pragma unroll
    for (int i = 0; i < CH; i++) {
        int e = e0l[i];
        int loc = off[e]++;
        if (loc < CAP) g_tok[e * CAP + loc] = base_s + i;
    }
    if (tid == 0 && out_size > (long long)S * MDIM) {
        float loss = 0.f;
#pragma unroll
        for (int e = 0; e < E; e++) loss += s_me[0][e] * (float)tot[e];
        loss *= (float)E / ((float)S * (float)S);
        d_out[(long long)S * MDIM] = loss;
    }
}

// ---------------- prep: we fp32 -> fp16 hi/lo ----------------
__global__ void __launch_bounds__(256) split_we_kernel(const float* __restrict__ we) {
    size_t i = (size_t)blockIdx.x * 256 + threadIdx.x;
    float4 v = ((const float4*)we)[i];
    __half h0 = __float2half_rn(v.x), h1 = __float2half_rn(v.y);
    __half h2 = __float2half_rn(v.z), h3 = __float2half_rn(v.w);
    __half2* oh = (__half2*)g_weh + i * 2;
    __half2* ol = (__half2*)g_wel + i * 2;
    oh[0] = __halves2half2(h0, h1);
    oh[1] = __halves2half2(h2, h3);
    ol[0] = __halves2half2(__float2half_rn(v.x - __half2float(h0)),
                           __float2half_rn(v.y - __half2float(h1)));
    ol[1] = __halves2half2(__float2half_rn(v.z - __half2float(h2)),
                           __float2half_rn(v.w - __half2float(h3)));
}

// ---------------- kernel 3: grouped GEMM, 128x256x32, 4-stage, 2-term fp16 ----------------
#define A_ROWB 80
#define B_ROWB 528
#define A_TILE (BM * A_ROWB)            // 10240
#define B_TILE (BK * B_ROWB)            // 16896
#define STG_AH 0
#define STG_BH (A_TILE)
#define STG_BL (A_TILE + B_TILE)
#define STG_SZ (A_TILE + 2 * B_TILE)    // 44032
#define STAGES 4
#define SMEM_BYTES (STAGES * STG_SZ)    // 176128

__global__ void __launch_bounds__(512) moe_gemm_mma(float* __restrict__ out) {
    int e  = blockIdx.z;
    int ne = g_ne[e];
    int r0 = blockIdx.y * BM;
    if (r0 >= ne) return;
    int n0 = blockIdx.x * BN;

    extern __shared__ __align__(16) char sm[];
    uint32_t sb = smem_u32(sm);
    __shared__ int   s_toks[BM];
    __shared__ float s_gts[BM];

    int tid = threadIdx.x;
    int wid = tid >> 5, lane = tid & 31;

    if (tid < BM) {
        int r = r0 + tid;
        int t = (r < ne) ? g_tok[e * CAP + r] : -1;
        s_toks[tid] = t;
        s_gts[tid]  = (t >= 0) ? g_gate[t] : 0.f;
    }
    __syncthreads();

    // A load: 128 rows x 64B; thread -> (row=tid>>2, seg=tid&3)
    int arow = tid >> 2, aseg = tid & 3;
    int atok = s_toks[arow];
    const char* axh = (const char*)(g_xh + ((atok >= 0 ? (size_t)atok : 0) * MDIM)) + aseg * 16;
    uint32_t abytes = (atok >= 0) ? 16u : 0u;
    uint32_t adst = arow * A_ROWB + aseg * 16;

    // B load: 32 rows x 512B; thread -> (row=tid>>4, 2 chunks of 16B, 256B apart)
    int brow = tid >> 4, bc = tid & 15;
    const char* bwh = (const char*)(g_weh + ((size_t)e << 20) + (size_t)brow * MDIM + n0) + bc * 16;
    const char* bwl = (const char*)(g_wel + ((size_t)e << 20) + (size_t)brow * MDIM + n0) + bc * 16;
    uint32_t bdst = brow * B_ROWB + bc * 16;
    const size_t bkstep = (size_t)BK * MDIM * 2;

    auto issue = [&](int kc, int st) {
        uint32_t so = sb + st * STG_SZ;
        size_t akoff = (size_t)kc * BK * 2;
        cp_async16(so + STG_AH + adst, axh + akoff, abytes);
        size_t bko = (size_t)kc * bkstep;
#pragma unroll
        for (int j = 0; j < 2; j++) {
            cp_async16(so + STG_BH + bdst + j * 256, bwh + bko + j * 256, 16u);
            cp_async16(so + STG_BL + bdst + j * 256, bwl + bko + j * 256, 16u);
        }
        CP_COMMIT();
    };

    int wm = wid & 3, wn = wid >> 2;   // warp tile 32m x 64n
    float acc[2][8][4];
#pragma unroll
    for (int a = 0; a < 2; a++)
#pragma unroll
        for (int b = 0; b < 8; b++)
#pragma unroll
            for (int c2 = 0; c2 < 4; c2++) acc[a][b][c2] = 0.f;

    issue(0, 0);
    issue(1, 1);
    issue(2, 2);

    int st = 0;
    for (int i = 0; i < NKC; i++) {
        if (i + 1 < NKC) { CP_WAIT(2); } else { CP_WAIT(0); }
        __syncthreads();
        if (i + 3 < NKC) {
            int nst = st + 3; if (nst >= STAGES) nst -= STAGES;
            issue(i + 3, nst);
        }

        uint32_t so  = sb + st * STG_SZ;
        uint32_t AHs = so + STG_AH;
        uint32_t BHs = so + STG_BH;
        uint32_t BLs = so + STG_BL;

#pragma unroll
        for (int ks = 0; ks < 2; ks++) {
            uint32_t ah[2][4], bh[4][4], bl[4][4];
            uint32_t aoff = ks * 32 + 16 * (lane >> 4);
#pragma unroll
            for (int mt = 0; mt < 2; mt++) {
                uint32_t row = wm * 32 + mt * 16 + (lane & 15);
                ldmat_x4(ah[mt], AHs + row * A_ROWB + aoff);
            }
            uint32_t brow16 = ks * 16 + (lane & 7) + 8 * ((lane >> 3) & 1);
#pragma unroll
            for (int nh = 0; nh < 4; nh++) {
                uint32_t boff = brow16 * B_ROWB + wn * 128 + nh * 32 + 16 * (lane >> 4);
                ldmat_x4_t(bh[nh], BHs + boff);
                ldmat_x4_t(bl[nh], BLs + boff);
            }
#pragma unroll
            for (int mt = 0; mt < 2; mt++) {
#pragma unroll
                for (int ns = 0; ns < 8; ns++) {
                    uint32_t b0h = bh[ns >> 1][(ns & 1) * 2], b1h = bh[ns >> 1][(ns & 1) * 2 + 1];
                    uint32_t b0l = bl[ns >> 1][(ns & 1) * 2], b1l = bl[ns >> 1][(ns & 1) * 2 + 1];
                    mma16816(acc[mt][ns], ah[mt], b0h, b1h);
                    mma16816(acc[mt][ns], ah[mt], b0l, b1l);
                }
            }
        }
        st++; if (st >= STAGES) st = 0;
    }

    // epilogue
#pragma unroll
    for (int mt = 0; mt < 2; mt++) {
#pragma unroll
        for (int half = 0; half < 2; half++) {
            int m = wm * 32 + mt * 16 + half * 8 + (lane >> 2);
            if (r0 + m < ne) {
                int   t = s_toks[m];
                float g = s_gts[m];
                float* orow = out + (size_t)t * MDIM + n0 + wn * 64 + (lane & 3) * 2;
#pragma unroll
                for (int ns = 0; ns < 8; ns++) {
                    float2 v;
                    v.x = g * acc[mt][ns][half * 2 + 0];
                    v.y = g * acc[mt][ns][half * 2 + 1];
                    *(float2*)(orow + ns * 8) = v;
                }
            }
        }
    }
}

// ---------------- launcher ----------------
extern "C" void kernel_launch(void* const* d_in, const int* in_sizes, int n_in,
                              void* d_out, int out_size) {
    const float* x  = (const float*)d_in[0];
    const float* wg = (const float*)d_in[1];
    const float* we = (const float*)d_in[2];
    float* out = (float*)d_out;

    cudaMemsetAsync(d_out, 0, sizeof(float) * (size_t)S * MDIM, 0);

    split_we_kernel<<<(E * MDIM * MDIM / 4) / 256, 256>>>(we);
    gate_kernel<<<S / 8, 256>>>(x, wg);
    scan_kernel<<<1, 256>>>(out, (long long)out_size);

    cudaFuncSetAttribute(moe_gemm_mma, cudaFuncAttributeMaxDynamicSharedMemorySize, SMEM_BYTES);
    dim3 grid(MDIM / BN, CAP / BM, E);
    moe_gemm_mma<<<grid, 512, SMEM_BYTES>>>(out);
}

// round 8
// speedup vs baseline: 3.4825x; 1.0247x over previous
#include <cuda_runtime.h>
#include <cuda_fp16.h>
#include <stdint.h>

#define S    4096
#define MDIM 1024
#define E    8
#define CAP  1024
#define BM   128
#define BN   128
#define BK   32
#define NKC  (MDIM / BK)   // 32

// ---------------- scratch (device globals; no allocation) ----------------
__device__ int    g_e0[S];
__device__ float  g_gate[S];
__device__ float  g_me_part[512 * E];
__device__ int    g_tok[E * CAP];
__device__ int    g_ne[E];
__device__ __half g_xh[S * MDIM];                 // x rounded to fp16
__device__ __half g_weh[E * MDIM * MDIM];         // we hi (fp16), [e][k][n]
__device__ __half g_wel[E * MDIM * MDIM];         // we lo (fp16)

__device__ __forceinline__ uint32_t smem_u32(const void* p) {
    uint32_t a;
    asm("{ .reg .u64 t; cvta.to.shared.u64 t, %1; cvt.u32.u64 %0, t; }" : "=r"(a) : "l"(p));
    return a;
}
__device__ __forceinline__ void cp_async16(uint32_t dst, const void* src, uint32_t bytes) {
    asm volatile("cp.async.cg.shared.global [%0], [%1], 16, %2;"
                 :: "r"(dst), "l"(src), "r"(bytes) : "memory");
}
#define CP_COMMIT() asm volatile("cp.async.commit_group;" ::: "memory")
#define CP_WAIT(n)  asm volatile("cp.async.wait_group %0;" :: "n"(n) : "memory")

__device__ __forceinline__ void ldmat_x4(uint32_t* r, uint32_t addr) {
    asm volatile("ldmatrix.sync.aligned.m8n8.x4.shared.b16 {%0,%1,%2,%3}, [%4];"
                 : "=r"(r[0]), "=r"(r[1]), "=r"(r[2]), "=r"(r[3]) : "r"(addr));
}
__device__ __forceinline__ void ldmat_x4_t(uint32_t* r, uint32_t addr) {
    asm volatile("ldmatrix.sync.aligned.m8n8.x4.trans.shared.b16 {%0,%1,%2,%3}, [%4];"
                 : "=r"(r[0]), "=r"(r[1]), "=r"(r[2]), "=r"(r[3]) : "r"(addr));
}
__device__ __forceinline__ void mma16816(float* c, const uint32_t* a, uint32_t b0, uint32_t b1) {
    asm volatile("mma.sync.aligned.m16n8k16.row.col.f32.f16.f16.f32 "
                 "{%0,%1,%2,%3}, {%4,%5,%6,%7}, {%8,%9}, {%0,%1,%2,%3};"
                 : "+f"(c[0]), "+f"(c[1]), "+f"(c[2]), "+f"(c[3])
                 : "r"(a[0]), "r"(a[1]), "r"(a[2]), "r"(a[3]), "r"(b0), "r"(b1));
}

// ---------------- kernel 1: gating + fused x->fp16 + me partials ----------------
__global__ void __launch_bounds__(256) gate_kernel(const float* __restrict__ x,
                                                   const float* __restrict__ wg) {
    __shared__ float wgs[E * MDIM];
    __shared__ float s_pr[8][E];
    int tid = threadIdx.x;
    for (int i = tid; i < E * MDIM / 4; i += 256)
        ((float4*)wgs)[i] = ((const float4*)wg)[i];
    __syncthreads();

    int warp = tid >> 5, lane = tid & 31;
    int s = blockIdx.x * 8 + warp;
    const float4* xr = (const float4*)(x + (size_t)s * MDIM);
    __half2* xh = (__half2*)(g_xh + (size_t)s * MDIM);
    float acc[E];
#pragma unroll
    for (int e = 0; e < E; e++) acc[e] = 0.f;
#pragma unroll
    for (int it = 0; it < MDIM / 128; it++) {
        int k4 = it * 32 + lane;
        float4 xv = xr[k4];
        xh[k4 * 2 + 0] = __halves2half2(__float2half_rn(xv.x), __float2half_rn(xv.y));
        xh[k4 * 2 + 1] = __halves2half2(__float2half_rn(xv.z), __float2half_rn(xv.w));
#pragma unroll
        for (int e = 0; e < E; e++) {
            float4 wv = ((const float4*)(wgs + e * MDIM))[k4];
            acc[e] += xv.x * wv.x + xv.y * wv.y + xv.z * wv.z + xv.w * wv.w;
        }
    }
#pragma unroll
    for (int e = 0; e < E; e++) {
#pragma unroll
        for (int off = 16; off; off >>= 1)
            acc[e] += __shfl_xor_sync(0xffffffffu, acc[e], off);
    }
    if (lane == 0) {
        float mx = acc[0]; int ei = 0;
#pragma unroll
        for (int e = 1; e < E; e++) if (acc[e] > mx) { mx = acc[e]; ei = e; }
        float ex[E]; float sum = 0.f;
#pragma unroll
        for (int e = 0; e < E; e++) { ex[e] = expf(acc[e] - mx); sum += ex[e]; }
        float inv = 1.f / sum;
#pragma unroll
        for (int e = 0; e < E; e++) s_pr[warp][e] = ex[e] * inv;
        g_e0[s]   = ei;
        g_gate[s] = ex[ei] * inv;
    }
    __syncthreads();
    if (tid < E) {
        float m = 0.f;
#pragma unroll
        for (int w = 0; w < 8; w++) m += s_pr[w][tid];
        g_me_part[blockIdx.x * E + tid] = m;
    }
}

// ---------------- kernel 2: ordered prefix scan + loss ----------------
__global__ void __launch_bounds__(256) scan_kernel(float* __restrict__ d_out,
                                                   long long out_size) {
    const int T = 256, CH = S / T;  // 16
    __shared__ int   cnt[T][E];
    __shared__ float s_me[32][E];
    __shared__ int   tot[E];
    int tid = threadIdx.x;

    int e0l[CH];
    {
        const int4* p = (const int4*)(g_e0 + tid * CH);
#pragma unroll
        for (int q = 0; q < CH / 4; q++) {
            int4 v = p[q];
            e0l[q * 4 + 0] = v.x; e0l[q * 4 + 1] = v.y;
            e0l[q * 4 + 2] = v.z; e0l[q * 4 + 3] = v.w;
        }
    }
    int c[E];
#pragma unroll
    for (int e = 0; e < E; e++) c[e] = 0;
#pragma unroll
    for (int i = 0; i < CH; i++) c[e0l[i]]++;
#pragma unroll
    for (int e = 0; e < E; e++) cnt[tid][e] = c[e];

    {
        int e = tid & 7, grp = tid >> 3;
        float m = 0.f;
#pragma unroll
        for (int j = 0; j < 16; j++) m += g_me_part[(grp * 16 + j) * E + e];
        s_me[grp][e] = m;
    }
    __syncthreads();
    for (int stride = 16; stride; stride >>= 1) {
        if (tid < stride * E) {
            int e = tid & 7, grp = tid >> 3;
            s_me[grp][e] += s_me[grp + stride][e];
        }
        __syncthreads();
    }

    if (tid < E) {
        int run = 0;
        for (int t = 0; t < T; t++) { int v = cnt[t][tid]; cnt[t][tid] = run; run += v; }
        tot[tid] = run;
        g_ne[tid] = run < CAP ? run : CAP;
    }
    __syncthreads();
    int off[E];
#pragma unroll
    for (int e = 0; e < E; e++) off[e] = cnt[tid][e];
    int base_s = tid * CH;
#pragma unroll
    for (int i = 0; i < CH; i++) {
        int e = e0l[i];
        int loc = off[e]++;
        if (loc < CAP) g_tok[e * CAP + loc] = base_s + i;
    }
    if (tid == 0 && out_size > (long long)S * MDIM) {
        float loss = 0.f;
#pragma unroll
        for (int e = 0; e < E; e++) loss += s_me[0][e] * (float)tot[e];
        loss *= (float)E / ((float)S * (float)S);
        d_out[(long long)S * MDIM] = loss;
    }
}

// ---------------- prep: we fp32 -> fp16 hi/lo ----------------
__global__ void __launch_bounds__(256) split_we_kernel(const float* __restrict__ we) {
    size_t i = (size_t)blockIdx.x * 256 + threadIdx.x;
    float4 v = ((const float4*)we)[i];
    __half h0 = __float2half_rn(v.x), h1 = __float2half_rn(v.y);
    __half h2 = __float2half_rn(v.z), h3 = __float2half_rn(v.w);
    __half2* oh = (__half2*)g_weh + i * 2;
    __half2* ol = (__half2*)g_wel + i * 2;
    oh[0] = __halves2half2(h0, h1);
    oh[1] = __halves2half2(h2, h3);
    ol[0] = __halves2half2(__float2half_rn(v.x - __half2float(h0)),
                           __float2half_rn(v.y - __half2float(h1)));
    ol[1] = __halves2half2(__float2half_rn(v.z - __half2float(h2)),
                           __float2half_rn(v.w - __half2float(h3)));
}

// ---------------- kernel 3: grouped GEMM, 128x128x32, 256thr, 2 CTA/SM ----------------
#define A_ROWB 80
#define B_ROWB 272
#define A_TILE (BM * A_ROWB)            // 10240
#define B_TILE (BK * B_ROWB)            // 8704
#define STG_AH 0
#define STG_BH (A_TILE)
#define STG_BL (A_TILE + B_TILE)
#define STG_SZ (A_TILE + 2 * B_TILE)    // 27648
#define STAGES 4
#define SMEM_BYTES (STAGES * STG_SZ)    // 110592

__global__ void __launch_bounds__(256, 2) moe_gemm_mma(float* __restrict__ out) {
    int e  = blockIdx.z;
    int ne = g_ne[e];
    int r0 = blockIdx.y * BM;
    if (r0 >= ne) return;
    int n0 = blockIdx.x * BN;

    extern __shared__ __align__(16) char sm[];
    uint32_t sb = smem_u32(sm);
    __shared__ int   s_toks[BM];
    __shared__ float s_gts[BM];

    int tid = threadIdx.x;
    int wid = tid >> 5, lane = tid & 31;

    if (tid < BM) {
        int r = r0 + tid;
        int t = (r < ne) ? g_tok[e * CAP + r] : -1;
        s_toks[tid] = t;
        s_gts[tid]  = (t >= 0) ? g_gate[t] : 0.f;
    }
    __syncthreads();

    // A load: 128 rows x 64B; thread -> (row=tid>>1, 2 chunks of 16B)
    int arow = tid >> 1, aseg = tid & 1;
    int atok = s_toks[arow];
    const char* axh = (const char*)(g_xh + ((atok >= 0 ? (size_t)atok : 0) * MDIM)) + aseg * 32;
    uint32_t abytes = (atok >= 0) ? 16u : 0u;
    uint32_t adst = arow * A_ROWB + aseg * 32;

    // B load: 32 rows x 256B per plane; thread -> (row=tid>>3, 2 chunks 128B apart)
    int brow = tid >> 3, bc = tid & 7;
    const char* bwh = (const char*)(g_weh + ((size_t)e << 20) + (size_t)brow * MDIM + n0) + bc * 16;
    const char* bwl = (const char*)(g_wel + ((size_t)e << 20) + (size_t)brow * MDIM + n0) + bc * 16;
    uint32_t bdst = brow * B_ROWB + bc * 16;
    const size_t bkstep = (size_t)BK * MDIM * 2;

    auto issue = [&](int kc, int st) {
        uint32_t so = sb + st * STG_SZ;
        size_t akoff = (size_t)kc * BK * 2;
        cp_async16(so + STG_AH + adst,      axh + akoff,      abytes);
        cp_async16(so + STG_AH + adst + 16, axh + akoff + 16, abytes);
        size_t bko = (size_t)kc * bkstep;
#pragma unroll
        for (int j = 0; j < 2; j++) {
            cp_async16(so + STG_BH + bdst + j * 128, bwh + bko + j * 128, 16u);
            cp_async16(so + STG_BL + bdst + j * 128, bwl + bko + j * 128, 16u);
        }
        CP_COMMIT();
    };

    int wm = wid & 3, wn = wid >> 2;   // 8 warps: 4m x 2n, warp tile 32m x 64n
    float acc[2][8][4];
#pragma unroll
    for (int a = 0; a < 2; a++)
#pragma unroll
        for (int b = 0; b < 8; b++)
#pragma unroll
            for (int c2 = 0; c2 < 4; c2++) acc[a][b][c2] = 0.f;

    issue(0, 0);
    issue(1, 1);
    issue(2, 2);

    int st = 0;
    for (int i = 0; i < NKC; i++) {
        if (i + 1 < NKC) { CP_WAIT(2); } else { CP_WAIT(0); }
        __syncthreads();
        if (i + 3 < NKC) {
            int nst = st + 3; if (nst >= STAGES) nst -= STAGES;
            issue(i + 3, nst);
        }

        uint32_t so  = sb + st * STG_SZ;
        uint32_t AHs = so + STG_AH;
        uint32_t BHs = so + STG_BH;
        uint32_t BLs = so + STG_BL;

#pragma unroll
        for (int ks = 0; ks < 2; ks++) {
            uint32_t ah[2][4], bh[4][4], bl[4][4];
            uint32_t aoff = ks * 32 + 16 * (lane >> 4);
#pragma unroll
            for (int mt = 0; mt < 2; mt++) {
                uint32_t row = wm * 32 + mt * 16 + (lane & 15);
                ldmat_x4(ah[mt], AHs + row * A_ROWB + aoff);
            }
            uint32_t brow16 = ks * 16 + (lane & 7) + 8 * ((lane >> 3) & 1);
#pragma unroll
            for (int nh = 0; nh < 4; nh++) {
                uint32_t boff = brow16 * B_ROWB + wn * 128 + nh * 32 + 16 * (lane >> 4);
                ldmat_x4_t(bh[nh], BHs + boff);
                ldmat_x4_t(bl[nh], BLs + boff);
            }
#pragma unroll
            for (int mt = 0; mt < 2; mt++) {
#pragma unroll
                for (int ns = 0; ns < 8; ns++) {
                    uint32_t b0h = bh[ns >> 1][(ns & 1) * 2], b1h = bh[ns >> 1][(ns & 1) * 2 + 1];
                    uint32_t b0l = bl[ns >> 1][(ns & 1) * 2], b1l = bl[ns >> 1][(ns & 1) * 2 + 1];
                    mma16816(acc[mt][ns], ah[mt], b0h, b1h);
                    mma16816(acc[mt][ns], ah[mt], b0l, b1l);
                }
            }
        }
        st++; if (st >= STAGES) st = 0;
    }

    // epilogue
#pragma unroll
    for (int mt = 0; mt < 2; mt++) {
#pragma unroll
        for (int half = 0; half < 2; half++) {
            int m = wm * 32 + mt * 16 + half * 8 + (lane >> 2);
            if (r0 + m < ne) {
                int   t = s_toks[m];
                float g = s_gts[m];
                float* orow = out + (size_t)t * MDIM + n0 + wn * 64 + (lane & 3) * 2;
#pragma unroll
                for (int ns = 0; ns < 8; ns++) {
                    float2 v;
                    v.x = g * acc[mt][ns][half * 2 + 0];
                    v.y = g * acc[mt][ns][half * 2 + 1];
                    *(float2*)(orow + ns * 8) = v;
                }
            }
        }
    }
}

// ---------------- launcher ----------------
extern "C" void kernel_launch(void* const* d_in, const int* in_sizes, int n_in,
                              void* d_out, int out_size) {
    const float* x  = (const float*)d_in[0];
    const float* wg = (const float*)d_in[1];
    const float* we = (const float*)d_in[2];
    float* out = (float*)d_out;

    // lazy one-time stream/event creation (first call is the uncaptured
    // correctness run; capture replays only the launches + fork/join edges)
    static cudaStream_t s2 = nullptr;
    static cudaEvent_t evFork = nullptr, evJoin = nullptr;
    if (s2 == nullptr) {
        cudaStreamCreateWithFlags(&s2, cudaStreamNonBlocking);
        cudaEventCreateWithFlags(&evFork, cudaEventDisableTiming);
        cudaEventCreateWithFlags(&evJoin, cudaEventDisableTiming);
    }

    // fork: side stream does memset + weight split; main stream gate + scan
    cudaEventRecord(evFork, 0);
    cudaStreamWaitEvent(s2, evFork, 0);

    cudaMemsetAsync(d_out, 0, sizeof(float) * (size_t)S * MDIM, s2);
    split_we_kernel<<<(E * MDIM * MDIM / 4) / 256, 256, 0, s2>>>(we);

    gate_kernel<<<S / 8, 256>>>(x, wg);
    scan_kernel<<<1, 256>>>(out, (long long)out_size);

    // join
    cudaEventRecord(evJoin, s2);
    cudaStreamWaitEvent(0, evJoin, 0);

    cudaFuncSetAttribute(moe_gemm_mma, cudaFuncAttributeMaxDynamicSharedMemorySize, SMEM_BYTES);
    dim3 grid(MDIM / BN, CAP / BM, E);
    moe_gemm_mma<<<grid, 256, SMEM_BYTES>>>(out);
}